// round 1
// baseline (speedup 1.0000x reference)
#include <cuda_runtime.h>

// ---------------------------------------------------------------------------
// Problem constants
// ---------------------------------------------------------------------------
#define Bb 8
#define Ss 32
#define Nn 1024
#define Ff 4
#define Hh 128
#define NBROWS (Nn * Bb)        // 8192 rows (node-major, batch inner)
#define NBH (NBROWS * Hh)       // 1048576
#define NHf (Nn * Hh)           // 131072 flat per-batch hidden size
#define KC 136                  // concat K (4 + 128) padded to 136 (mult of 8)
#define G3 384                  // 3*H

// ---------------------------------------------------------------------------
// Scratch (device globals; no allocation allowed)
// ---------------------------------------------------------------------------
__device__ float g_Xt[Nn * Ss * Bb * Ff];   // x transposed to (N,S,B,F)
__device__ float g_AX[Nn * Ss * Bb * Ff];   // adj @ x for all steps, (N,S,B,F)
__device__ float g_hid[NBH];                // hidden, layout (n, b, h)
__device__ float g_AH[Nn * Bb * Hh];        // adj @ hid, layout (n, [b,h])
__device__ float g_AC[NBROWS * KC];         // concat [ax | ah | 0pad], rows (n*B+b)
__device__ float g_Wc[KC * 512];            // [W1 | W2] padded, (136,512)
__device__ float g_G[NBROWS * 512];         // gate pre-activations per step
__device__ float g_csum[NBH];               // sum over s of hnew == ctx
__device__ float g_WihT[128 * 512];         // W_ih transposed (128,512)
__device__ float g_WhhT[128 * 512];         // W_hh transposed (128,512)
__device__ float g_Gc[NBROWS * 512];        // ctx @ W_ih^T (fixed across dec steps)
__device__ float g_Gd[NBROWS * 512];        // hx @ W_hh^T per step
__device__ float g_hx[NBH];
__device__ float g_cx[NBH];

__device__ __forceinline__ float sigm(float x) { return 1.f / (1.f + __expf(-x)); }

// ---------------------------------------------------------------------------
// Tiled fp32 SGEMM: C = A(MxK) @ B(KxN), row-major, no bounds checks.
// Requires: M % BM == 0, N % BN == 0, K % 8 == 0, BM == 128, 256 threads.
// ---------------------------------------------------------------------------
template <int BM, int BN, int TM, int TN>
__global__ void __launch_bounds__(256) sgemm(
    const float* __restrict__ A, const float* __restrict__ Bm,
    float* __restrict__ C, int M, int N, int K)
{
    constexpr int BK = 8;
    constexpr int TX = BN / TN;
    __shared__ float As[BK][BM + 4];
    __shared__ float Bs[BK][BN + 4];

    const int tid = threadIdx.x;
    const int bm = blockIdx.y * BM;
    const int bn = blockIdx.x * BN;
    const int tx = tid % TX;
    const int ty = tid / TX;

    // A loader: BM=128 -> each thread one float4 along K
    const int arow = tid >> 1;            // 0..127
    const int acol = (tid & 1) << 2;      // 0 or 4
    const float* Aptr = A + (size_t)(bm + arow) * K + acol;

    float acc[TM][TN] = {};

    for (int k0 = 0; k0 < K; k0 += BK) {
        float4 a4 = *(const float4*)(Aptr + k0);
        As[acol + 0][arow] = a4.x;
        As[acol + 1][arow] = a4.y;
        As[acol + 2][arow] = a4.z;
        As[acol + 3][arow] = a4.w;
        if (BN == 128) {
            const int rb = tid >> 5, cb = (tid & 31) << 2;
            *(float4*)&Bs[rb][cb] =
                *(const float4*)(Bm + (size_t)(k0 + rb) * N + bn + cb);
        } else {  // BN == 64
            const int rb = tid >> 5, cb = (tid & 31) << 1;
            *(float2*)&Bs[rb][cb] =
                *(const float2*)(Bm + (size_t)(k0 + rb) * N + bn + cb);
        }
        __syncthreads();
#pragma unroll
        for (int k = 0; k < BK; k++) {
            float ar[TM], br[TN];
#pragma unroll
            for (int i = 0; i < TM; i++) ar[i] = As[k][ty * TM + i];
#pragma unroll
            for (int j = 0; j < TN; j++) br[j] = Bs[k][tx * TN + j];
#pragma unroll
            for (int i = 0; i < TM; i++)
#pragma unroll
                for (int j = 0; j < TN; j++) acc[i][j] += ar[i] * br[j];
        }
        __syncthreads();
    }
#pragma unroll
    for (int i = 0; i < TM; i++) {
        float* cp = C + (size_t)(bm + ty * TM + i) * N + bn + tx * TN;
#pragma unroll
        for (int j = 0; j < TN; j += 4) {
            float4 v = make_float4(acc[i][j], acc[i][j + 1], acc[i][j + 2], acc[i][j + 3]);
            *(float4*)(cp + j) = v;
        }
    }
}

// ---------------------------------------------------------------------------
// Small kernels
// ---------------------------------------------------------------------------
__global__ void k_zero()
{
    int idx = blockIdx.x * blockDim.x + threadIdx.x;
    if (idx < NBH) {
        g_hid[idx] = 0.f;
        g_csum[idx] = 0.f;
        g_hx[idx] = 0.f;
        g_cx[idx] = 0.f;
    }
    if (idx < NBROWS) {  // zero the 4 K-pad columns of AC once per launch
        g_AC[idx * KC + 132] = 0.f;
        g_AC[idx * KC + 133] = 0.f;
        g_AC[idx * KC + 134] = 0.f;
        g_AC[idx * KC + 135] = 0.f;
    }
}

// Build Wc = [W1 | W2] (K-padded) and the transposed decoder weights.
__global__ void k_prep(const float* __restrict__ W1, const float* __restrict__ W2,
                       const float* __restrict__ Wih, const float* __restrict__ Whh)
{
    int idx = blockIdx.x * blockDim.x + threadIdx.x;
    if (idx < KC * 512) {
        int k = idx / 512, j = idx % 512;
        float v = 0.f;
        if (k < 132) v = (j < G3) ? W1[k * G3 + j] : W2[k * Hh + (j - G3)];
        g_Wc[idx] = v;
    }
    if (idx < 128 * 512) {
        int k = idx >> 9, j = idx & 511;
        g_WihT[idx] = Wih[j * 128 + k];
        g_WhhT[idx] = Whh[j * 128 + k];
    }
}

// x (B,S,N,F) -> Xt (N,S,B,F); F=4 so one float4 per (n,s,b)
__global__ void k_tx(const float* __restrict__ x)
{
    int idx = blockIdx.x * blockDim.x + threadIdx.x;  // over N*S*B = 262144
    if (idx >= Nn * Ss * Bb) return;
    int n = idx / (Ss * Bb);
    int r = idx % (Ss * Bb);
    int s = r / Bb;
    int b = r % Bb;
    ((float4*)g_Xt)[idx] = ((const float4*)x)[(size_t)(b * Ss + s) * Nn + n];
}

// Pack AC row r=(n*B+b): [AX[n,s,b,:4] | AH[n, b*128 : b*128+128]]
__global__ void k_pack(int s)
{
    int r = blockIdx.x * 8 + (threadIdx.x >> 5);   // 8192 rows, 1 warp per row
    int lane = threadIdx.x & 31;
    int n = r >> 3;
    int b = r & 7;
    float4 v = ((const float4*)g_AH)[n * 256 + b * 32 + lane];
    ((float4*)(g_AC + (size_t)r * KC + 4))[lane] = v;
    if (lane == 0) {
        ((float4*)(g_AC + (size_t)r * KC))[0] =
            ((const float4*)g_AX)[(n * Ss + s) * Bb + b];
    }
}

// Encoder elementwise: reproduces the flat-chunk gate indexing exactly.
// cell == 0 always => hnew = sig(og)*tanh(sig(ig)*tanh(cs))
__global__ void k_enc_elem(const float* __restrict__ b1, const float* __restrict__ b2)
{
    int idx = blockIdx.x * blockDim.x + threadIdx.x;  // over B*NHf = 1048576
    if (idx >= Bb * NHf) return;
    int b = idx / NHf;
    int j = idx % NHf;
    int n = j >> 7;
    int h = j & 127;
    int ji = j + NHf;            // ig flat offset
    int ni = ji / G3, ci = ji % G3;
    int jo = j + 2 * NHf;        // og flat offset
    int no = jo / G3, co = jo % G3;

    float igp = g_G[(size_t)(ni * Bb + b) * 512 + ci] + b1[ci];
    float ogp = g_G[(size_t)(no * Bb + b) * 512 + co] + b1[co];
    float csp = g_G[(size_t)(n * Bb + b) * 512 + G3 + h] + b2[h];

    float hn = sigm(ogp) * tanhf(sigm(igp) * tanhf(csp));
    int o = (n * Bb + b) * Hh + h;
    g_hid[o] = hn;
    g_csum[o] += hn;
}

// Decoder LSTM elementwise. Gate order from split: ig, fg, gg, og.
__global__ void k_lstm(const float* __restrict__ bih, const float* __restrict__ bhh)
{
    int idx = blockIdx.x * blockDim.x + threadIdx.x;  // over NBH
    if (idx >= NBH) return;
    int r = idx >> 7;
    int h = idx & 127;
    const float* gc = g_Gc + (size_t)r * 512;
    const float* gd = g_Gd + (size_t)r * 512;
    float ig = sigm(gc[h] + gd[h] + bih[h] + bhh[h]);
    float fg = sigm(gc[128 + h] + gd[128 + h] + bih[128 + h] + bhh[128 + h]);
    float gg = tanhf(gc[256 + h] + gd[256 + h] + bih[256 + h] + bhh[256 + h]);
    float og = sigm(gc[384 + h] + gd[384 + h] + bih[384 + h] + bhh[384 + h]);
    float cx = fg * g_cx[idx] + ig * gg;
    g_cx[idx] = cx;
    g_hx[idx] = og * tanhf(cx);
}

// out[b][n][h] = hx[(n*B+b)][h]
__global__ void k_out(float* __restrict__ out)
{
    int idx = blockIdx.x * blockDim.x + threadIdx.x;
    if (idx >= NBH) return;
    int b = idx / (Nn * Hh);
    int rem = idx % (Nn * Hh);
    int n = rem >> 7;
    int h = rem & 127;
    out[idx] = g_hx[(size_t)(n * Bb + b) * Hh + h];
}

// ---------------------------------------------------------------------------
// Launch
// ---------------------------------------------------------------------------
extern "C" void kernel_launch(void* const* d_in, const int* in_sizes, int n_in,
                              void* d_out, int out_size)
{
    (void)in_sizes; (void)n_in; (void)out_size;
    const float* x   = (const float*)d_in[0];
    const float* adj = (const float*)d_in[1];
    const float* W1  = (const float*)d_in[2];
    const float* b1  = (const float*)d_in[3];
    const float* W2  = (const float*)d_in[4];
    const float* b2  = (const float*)d_in[5];
    const float* Wih = (const float*)d_in[6];
    const float* Whh = (const float*)d_in[7];
    const float* bih = (const float*)d_in[8];
    const float* bhh = (const float*)d_in[9];
    float* out = (float*)d_out;

    float *pXt, *pAX, *pHid, *pAH, *pAC, *pWc, *pG, *pCs, *pWihT, *pWhhT, *pGc, *pGd, *pHx;
    cudaGetSymbolAddress((void**)&pXt, g_Xt);
    cudaGetSymbolAddress((void**)&pAX, g_AX);
    cudaGetSymbolAddress((void**)&pHid, g_hid);
    cudaGetSymbolAddress((void**)&pAH, g_AH);
    cudaGetSymbolAddress((void**)&pAC, g_AC);
    cudaGetSymbolAddress((void**)&pWc, g_Wc);
    cudaGetSymbolAddress((void**)&pG, g_G);
    cudaGetSymbolAddress((void**)&pCs, g_csum);
    cudaGetSymbolAddress((void**)&pWihT, g_WihT);
    cudaGetSymbolAddress((void**)&pWhhT, g_WhhT);
    cudaGetSymbolAddress((void**)&pGc, g_Gc);
    cudaGetSymbolAddress((void**)&pGd, g_Gd);
    cudaGetSymbolAddress((void**)&pHx, g_hx);

    k_zero<<<4096, 256>>>();
    k_prep<<<(KC * 512 + 255) / 256, 256>>>(W1, W2, Wih, Whh);
    k_tx<<<1024, 256>>>(x);

    // AX = adj @ Xt  : (1024x1024)@(1024x1024)  -> all-steps precompute
    sgemm<128, 64, 8, 4><<<dim3(16, 8), 256>>>(adj, pXt, pAX, Nn, Ss * Bb * Ff, Nn);

    // ---------------- Encoder: 32 recurrent steps ----------------
    for (int s = 0; s < Ss; s++) {
        // AH = adj @ hid : (1024x1024)@(1024x1024) viewing hid as (N, B*H)
        sgemm<128, 64, 8, 4><<<dim3(16, 8), 256>>>(adj, pHid, pAH, Nn, Bb * Hh, Nn);
        k_pack<<<1024, 256>>>(s);
        // G = AC @ Wc : (8192x136)@(136x512)
        sgemm<128, 128, 8, 8><<<dim3(4, 64), 256>>>(pAC, pWc, pG, NBROWS, 512, KC);
        k_enc_elem<<<4096, 256>>>(b1, b2);
    }

    // ---------------- Decoder: ctx is constant = csum ----------------
    // Gc = ctx @ W_ih^T : (8192x128)@(128x512), computed once
    sgemm<128, 128, 8, 8><<<dim3(4, 64), 256>>>(pCs, pWihT, pGc, NBROWS, 512, 128);
    for (int t = 0; t < Ss; t++) {
        sgemm<128, 128, 8, 8><<<dim3(4, 64), 256>>>(pHx, pWhhT, pGd, NBROWS, 512, 128);
        k_lstm<<<4096, 256>>>(bih, bhh);
    }

    k_out<<<4096, 256>>>(out);
}

// round 4
// speedup vs baseline: 2.0656x; 2.0656x over previous
#include <cuda_runtime.h>
#include <cuda_bf16.h>
#include <stdint.h>

// ---------------------------------------------------------------------------
// Problem constants
// ---------------------------------------------------------------------------
#define Bb 8
#define Ss 32
#define Nn 1024
#define Hh 128
#define NBROWS 8192
#define NBH 1048576
#define NHf 131072
#define G3 384
#define KAC 160                 // AC K (132) padded to 5*32

// ---------------------------------------------------------------------------
// Scratch (device globals; no allocation allowed)
// ---------------------------------------------------------------------------
__device__ __nv_bfloat16 g_adjH[1024 * 1024], g_adjL[1024 * 1024];
__device__ __nv_bfloat16 g_xTH[1024 * 1024], g_xTL[1024 * 1024];
__device__ __nv_bfloat16 g_hidTH[1024 * 1024], g_hidTL[1024 * 1024];
__device__ __nv_bfloat16 g_acH[8192 * KAC], g_acL[8192 * KAC];
__device__ __nv_bfloat16 g_wcH[512 * KAC], g_wcL[512 * KAC];
__device__ __nv_bfloat16 g_wihH[512 * 128], g_wihL[512 * 128];
__device__ __nv_bfloat16 g_whhH[512 * 128], g_whhL[512 * 128];
__device__ __nv_bfloat16 g_csH[8192 * 128], g_csL[8192 * 128];
__device__ __nv_bfloat16 g_hxH[8192 * 128], g_hxL[8192 * 128];

__device__ float g_WcT[512 * 132];
__device__ float g_AX[1024 * 1024];
__device__ float g_AH[1024 * 1024];
__device__ float g_G[NBROWS * 512];
__device__ float g_Gc[NBROWS * 512];
__device__ float g_Gd[NBROWS * 512];
__device__ float g_hid[NBH];
__device__ float g_csum[NBH];
__device__ float g_hx[NBH];
__device__ float g_cx[NBH];

// ---------------------------------------------------------------------------
// Helpers
// ---------------------------------------------------------------------------
__device__ __forceinline__ float sigm(float x) { return 1.f / (1.f + __expf(-x)); }

__device__ __forceinline__ uint32_t smem_u32(const void* p) {
    uint32_t a;
    asm("{ .reg .u64 t; cvta.to.shared.u64 t, %1; cvt.u32.u64 %0, t; }" : "=r"(a) : "l"(p));
    return a;
}

__device__ __forceinline__ void splitHL(float v, __nv_bfloat16& h, __nv_bfloat16& l) {
    h = __float2bfloat16(v);
    l = __float2bfloat16(v - __bfloat162float(h));
}

#define MMA_BF16(c, a, b)                                                     \
    asm volatile(                                                             \
        "mma.sync.aligned.m16n8k16.row.col.f32.bf16.bf16.f32 "                \
        "{%0,%1,%2,%3},{%4,%5,%6,%7},{%8,%9},{%0,%1,%2,%3};"                  \
        : "+f"((c)[0]), "+f"((c)[1]), "+f"((c)[2]), "+f"((c)[3])              \
        : "r"((a)[0]), "r"((a)[1]), "r"((a)[2]), "r"((a)[3]),                 \
          "r"((b)[0]), "r"((b)[1]))

#define CPASYNC16(s, g)                                                       \
    asm volatile("cp.async.cg.shared.global [%0], [%1], 16;" :: "r"(s), "l"(g))
#define CPCOMMIT() asm volatile("cp.async.commit_group;")
#define CPWAIT1()  asm volatile("cp.async.wait_group 1;")
#define CPWAIT0()  asm volatile("cp.async.wait_group 0;")

// ---------------------------------------------------------------------------
// 3xBF16 split GEMM via mma.sync (baseline PTX; runs on the tensor pipe).
// C[M x N] = A @ B^T.  A: [M][K] row-major bf16 hi/lo. B: [N][K] bf16 hi/lo.
// BM=64, BN=128, BK=32, 256 threads (8 warps: 2 along M x 4 along N).
// SMEM rows padded to 40 bf16 (80B) -> conflict-free fragment loads.
// grid = (N/128, M/64). K % 32 == 0.
// ---------------------------------------------------------------------------
#define STG_ELEMS 15360         // (64 + 64 + 128 + 128) * 40
#define SMEM_BYTES (2 * STG_ELEMS * 2)

__global__ void __launch_bounds__(256) gemm3(
    const __nv_bfloat16* __restrict__ Ah, const __nv_bfloat16* __restrict__ Al,
    const __nv_bfloat16* __restrict__ Bh, const __nv_bfloat16* __restrict__ Bl,
    float* __restrict__ C, int K, int N)
{
    extern __shared__ __nv_bfloat16 smem[];
    const uint32_t sbase = smem_u32(smem);

    const int tid = threadIdx.x;
    const int lane = tid & 31;
    const int wid = tid >> 5;
    const int wm = wid >> 2;          // 0..1
    const int wn = wid & 3;           // 0..3
    const int g = lane >> 2;          // 0..7
    const int ti = lane & 3;          // 0..3

    const int bm = blockIdx.y * 64;
    const int bn = blockIdx.x * 128;

    // loader indices
    const int arow = tid >> 2;        // 0..63
    const int akq = tid & 3;          // 0..3 (8 bf16 each)

    float acc[2][4][4];
#pragma unroll
    for (int i = 0; i < 2; i++)
#pragma unroll
        for (int j = 0; j < 4; j++)
#pragma unroll
            for (int v = 0; v < 4; v++) acc[i][j][v] = 0.f;

    const int nk = K >> 5;

    // ---- async stage loader ----
    auto load_stage = [&](int stage, int k0) {
        const uint32_t sb = sbase + stage * STG_ELEMS * 2;
        // A hi / lo : 64 rows x 32k
        {
            const uint32_t so = sb + (arow * 40 + akq * 8) * 2;
            CPASYNC16(so, Ah + (size_t)(bm + arow) * K + k0 + akq * 8);
            CPASYNC16(so + 2560 * 2, Al + (size_t)(bm + arow) * K + k0 + akq * 8);
        }
        // B hi / lo : 128 rows x 32k (two rows per thread)
#pragma unroll
        for (int rep = 0; rep < 2; rep++) {
            const int idx = tid + rep * 256;
            const int brow = idx >> 2;
            const int bkq = idx & 3;
            const uint32_t so = sb + (5120 + brow * 40 + bkq * 8) * 2;
            CPASYNC16(so, Bh + (size_t)(bn + brow) * K + k0 + bkq * 8);
            CPASYNC16(so + 5120 * 2, Bl + (size_t)(bn + brow) * K + k0 + bkq * 8);
        }
        CPCOMMIT();
    };

    load_stage(0, 0);

    for (int kt = 0; kt < nk; kt++) {
        if (kt + 1 < nk) { load_stage((kt + 1) & 1, (kt + 1) * 32); CPWAIT1(); }
        else             { CPWAIT0(); }
        __syncthreads();

        const __nv_bfloat16* sA = smem + (kt & 1) * STG_ELEMS;
        const __nv_bfloat16* sAl = sA + 2560;
        const __nv_bfloat16* sB = sA + 5120;
        const __nv_bfloat16* sBl = sA + 10240;

#pragma unroll
        for (int q = 0; q < 2; q++) {
            const int kb = q * 16 + 2 * ti;
            uint32_t ah[2][4], al[2][4], bh[4][2], bl[4][2];
#pragma unroll
            for (int mi = 0; mi < 2; mi++) {
                const int r0 = wm * 32 + mi * 16 + g;
                ah[mi][0] = *(const uint32_t*)&sA[r0 * 40 + kb];
                ah[mi][1] = *(const uint32_t*)&sA[(r0 + 8) * 40 + kb];
                ah[mi][2] = *(const uint32_t*)&sA[r0 * 40 + kb + 8];
                ah[mi][3] = *(const uint32_t*)&sA[(r0 + 8) * 40 + kb + 8];
                al[mi][0] = *(const uint32_t*)&sAl[r0 * 40 + kb];
                al[mi][1] = *(const uint32_t*)&sAl[(r0 + 8) * 40 + kb];
                al[mi][2] = *(const uint32_t*)&sAl[r0 * 40 + kb + 8];
                al[mi][3] = *(const uint32_t*)&sAl[(r0 + 8) * 40 + kb + 8];
            }
#pragma unroll
            for (int ni = 0; ni < 4; ni++) {
                const int c0 = wn * 32 + ni * 8 + g;
                bh[ni][0] = *(const uint32_t*)&sB[c0 * 40 + kb];
                bh[ni][1] = *(const uint32_t*)&sB[c0 * 40 + kb + 8];
                bl[ni][0] = *(const uint32_t*)&sBl[c0 * 40 + kb];
                bl[ni][1] = *(const uint32_t*)&sBl[c0 * 40 + kb + 8];
            }
#pragma unroll
            for (int mi = 0; mi < 2; mi++)
#pragma unroll
                for (int ni = 0; ni < 4; ni++) {
                    MMA_BF16(acc[mi][ni], ah[mi], bh[ni]);
                    MMA_BF16(acc[mi][ni], ah[mi], bl[ni]);
                    MMA_BF16(acc[mi][ni], al[mi], bh[ni]);
                }
        }
        __syncthreads();
    }

    // epilogue
#pragma unroll
    for (int mi = 0; mi < 2; mi++) {
        const int row = bm + wm * 32 + mi * 16 + g;
#pragma unroll
        for (int ni = 0; ni < 4; ni++) {
            const int col = bn + wn * 32 + ni * 8 + 2 * ti;
            float* cp0 = C + (size_t)row * N + col;
            float* cp1 = C + (size_t)(row + 8) * N + col;
            *(float2*)cp0 = make_float2(acc[mi][ni][0], acc[mi][ni][1]);
            *(float2*)cp1 = make_float2(acc[mi][ni][2], acc[mi][ni][3]);
        }
    }
}

// ---------------------------------------------------------------------------
// Converters (row-major hi/lo split)
// ---------------------------------------------------------------------------

// Generic: src (R x Kc fp32) -> dH/dL (R x Kp bf16), zero-padded. grid.y = row.
__global__ void c_splitHL(const float* __restrict__ src,
                          __nv_bfloat16* __restrict__ dH, __nv_bfloat16* __restrict__ dL,
                          int Kc, int Kp)
{
    const int row = blockIdx.y;
    const int k = blockIdx.x * 256 + threadIdx.x;
    if (k >= Kp) return;
    const float v = (k < Kc) ? src[(size_t)row * Kc + k] : 0.f;
    __nv_bfloat16 h, l;
    splitHL(v, h, l);
    dH[(size_t)row * Kp + k] = h;
    dL[(size_t)row * Kp + k] = l;
}

// x (B,S,N,F) -> xT rows j=s*32+b*4+f, cols k=n. grid (4, 1024).
__global__ void c_split_x(const float* __restrict__ x)
{
    const int j = blockIdx.y;
    const int k = blockIdx.x * 256 + threadIdx.x;
    const int s = j >> 5, b = (j >> 2) & 7, f = j & 3;
    const float v = x[((size_t)(b * Ss + s) * Nn + k) * 4 + f];
    __nv_bfloat16 h, l;
    splitHL(v, h, l);
    g_xTH[(size_t)j * 1024 + k] = h;
    g_xTL[(size_t)j * 1024 + k] = l;
}

// hid (n, j) -> hidT (j, n) with split; 32x32 smem tile transpose. grid (32, 32).
__global__ void c_split_hidT()
{
    __shared__ float tile[32][33];
    const int tx = threadIdx.x & 31, ty = threadIdx.x >> 5;  // 32 x 8
    const int n0 = blockIdx.y * 32, j0 = blockIdx.x * 32;
#pragma unroll
    for (int q = 0; q < 4; q++)
        tile[ty + q * 8][tx] = g_hid[(size_t)(n0 + ty + q * 8) * 1024 + j0 + tx];
    __syncthreads();
#pragma unroll
    for (int q = 0; q < 4; q++) {
        const int j = j0 + ty + q * 8;
        const int n = n0 + tx;
        __nv_bfloat16 h, l;
        splitHL(tile[tx][ty + q * 8], h, l);
        g_hidTH[(size_t)j * 1024 + n] = h;
        g_hidTL[(size_t)j * 1024 + n] = l;
    }
}

// AC rows r=n*8+b: k<4 = AX[n][s*32+b*4+k]; k<132 = AH[n][b*128+k-4]; pad 0.
__global__ void c_pack_ac(int s)
{
    const int r = blockIdx.x;
    const int k = threadIdx.x;          // 0..159
    const int n = r >> 3, b = r & 7;
    float v = 0.f;
    if (k < 4) v = g_AX[(size_t)n * 1024 + s * 32 + b * 4 + k];
    else if (k < 132) v = g_AH[(size_t)n * 1024 + b * 128 + (k - 4)];
    __nv_bfloat16 h, l;
    splitHL(v, h, l);
    g_acH[(size_t)r * KAC + k] = h;
    g_acL[(size_t)r * KAC + k] = l;
}

// ---------------------------------------------------------------------------
// Small kernels
// ---------------------------------------------------------------------------
__global__ void k_zero()
{
    const int idx = blockIdx.x * blockDim.x + threadIdx.x;
    if (idx < NBH) {
        g_hid[idx] = 0.f; g_csum[idx] = 0.f; g_hx[idx] = 0.f; g_cx[idx] = 0.f;
        g_hxH[idx] = __float2bfloat16(0.f);
        g_hxL[idx] = __float2bfloat16(0.f);
    }
}

// WcT[g][c] (512 x 132): g<384 -> W1[c][g]; else W2[c][g-384]
__global__ void k_prep(const float* __restrict__ W1, const float* __restrict__ W2)
{
    const int idx = blockIdx.x * 256 + threadIdx.x;
    if (idx >= 512 * 132) return;
    const int gg = idx / 132, c = idx - gg * 132;
    g_WcT[idx] = (gg < G3) ? W1[c * G3 + gg] : W2[c * Hh + (gg - G3)];
}

// Encoder elementwise (flat-chunk gate indexing; cell == 0 always)
__global__ void k_enc_elem(const float* __restrict__ b1, const float* __restrict__ b2)
{
    const int idx = blockIdx.x * blockDim.x + threadIdx.x;
    if (idx >= Bb * NHf) return;
    const int b = idx / NHf;
    const int j = idx - b * NHf;
    const int n = j >> 7;
    const int h = j & 127;
    const int ji = j + NHf;
    const int ni = ji / G3, ci = ji - ni * G3;
    const int jo = j + 2 * NHf;
    const int no = jo / G3, co = jo - no * G3;

    const float igp = g_G[(size_t)(ni * Bb + b) * 512 + ci] + b1[ci];
    const float ogp = g_G[(size_t)(no * Bb + b) * 512 + co] + b1[co];
    const float csp = g_G[(size_t)(n * Bb + b) * 512 + G3 + h] + b2[h];

    const float hn = sigm(ogp) * tanhf(sigm(igp) * tanhf(csp));
    const int o = (n * Bb + b) * Hh + h;
    g_hid[o] = hn;
    g_csum[o] += hn;
}

// Decoder LSTM elementwise + fused hx hi/lo split (row-major)
__global__ void k_lstm(const float* __restrict__ bih, const float* __restrict__ bhh)
{
    const int idx = blockIdx.x * blockDim.x + threadIdx.x;
    if (idx >= NBH) return;
    const int r = idx >> 7;
    const int h = idx & 127;
    const float* gc = g_Gc + (size_t)r * 512;
    const float* gd = g_Gd + (size_t)r * 512;
    const float ig = sigm(gc[h] + gd[h] + bih[h] + bhh[h]);
    const float fg = sigm(gc[128 + h] + gd[128 + h] + bih[128 + h] + bhh[128 + h]);
    const float gg = tanhf(gc[256 + h] + gd[256 + h] + bih[256 + h] + bhh[256 + h]);
    const float og = sigm(gc[384 + h] + gd[384 + h] + bih[384 + h] + bhh[384 + h]);
    const float cx = fg * g_cx[idx] + ig * gg;
    g_cx[idx] = cx;
    const float hxv = og * tanhf(cx);
    g_hx[idx] = hxv;
    __nv_bfloat16 hh, ll;
    splitHL(hxv, hh, ll);
    g_hxH[idx] = hh;
    g_hxL[idx] = ll;
}

__global__ void k_out(float* __restrict__ out)
{
    const int idx = blockIdx.x * blockDim.x + threadIdx.x;
    if (idx >= NBH) return;
    const int b = idx / (Nn * Hh);
    const int rem = idx - b * (Nn * Hh);
    const int n = rem >> 7;
    const int h = rem & 127;
    out[idx] = g_hx[(size_t)(n * Bb + b) * Hh + h];
}

// ---------------------------------------------------------------------------
// Launch
// ---------------------------------------------------------------------------
extern "C" void kernel_launch(void* const* d_in, const int* in_sizes, int n_in,
                              void* d_out, int out_size)
{
    (void)in_sizes; (void)n_in; (void)out_size;
    const float* x   = (const float*)d_in[0];
    const float* adj = (const float*)d_in[1];
    const float* W1  = (const float*)d_in[2];
    const float* b1  = (const float*)d_in[3];
    const float* W2  = (const float*)d_in[4];
    const float* b2  = (const float*)d_in[5];
    const float* Wih = (const float*)d_in[6];
    const float* Whh = (const float*)d_in[7];
    const float* bih = (const float*)d_in[8];
    const float* bhh = (const float*)d_in[9];
    float* out = (float*)d_out;

    cudaFuncSetAttribute(gemm3, cudaFuncAttributeMaxDynamicSharedMemorySize, SMEM_BYTES);

    __nv_bfloat16 *pAdjH, *pAdjL, *pXH, *pXL, *pHtH, *pHtL, *pAcH, *pAcL;
    __nv_bfloat16 *pWcH, *pWcL, *pWiH, *pWiL, *pWhH, *pWhL, *pCsH, *pCsL, *pHxH, *pHxL;
    float *pWcT, *pAX, *pAH, *pG, *pGc, *pGd, *pCs;
    cudaGetSymbolAddress((void**)&pAdjH, g_adjH);
    cudaGetSymbolAddress((void**)&pAdjL, g_adjL);
    cudaGetSymbolAddress((void**)&pXH, g_xTH);
    cudaGetSymbolAddress((void**)&pXL, g_xTL);
    cudaGetSymbolAddress((void**)&pHtH, g_hidTH);
    cudaGetSymbolAddress((void**)&pHtL, g_hidTL);
    cudaGetSymbolAddress((void**)&pAcH, g_acH);
    cudaGetSymbolAddress((void**)&pAcL, g_acL);
    cudaGetSymbolAddress((void**)&pWcH, g_wcH);
    cudaGetSymbolAddress((void**)&pWcL, g_wcL);
    cudaGetSymbolAddress((void**)&pWiH, g_wihH);
    cudaGetSymbolAddress((void**)&pWiL, g_wihL);
    cudaGetSymbolAddress((void**)&pWhH, g_whhH);
    cudaGetSymbolAddress((void**)&pWhL, g_whhL);
    cudaGetSymbolAddress((void**)&pCsH, g_csH);
    cudaGetSymbolAddress((void**)&pCsL, g_csL);
    cudaGetSymbolAddress((void**)&pHxH, g_hxH);
    cudaGetSymbolAddress((void**)&pHxL, g_hxL);
    cudaGetSymbolAddress((void**)&pWcT, g_WcT);
    cudaGetSymbolAddress((void**)&pAX, g_AX);
    cudaGetSymbolAddress((void**)&pAH, g_AH);
    cudaGetSymbolAddress((void**)&pG, g_G);
    cudaGetSymbolAddress((void**)&pGc, g_Gc);
    cudaGetSymbolAddress((void**)&pGd, g_Gd);
    cudaGetSymbolAddress((void**)&pCs, g_csum);

    k_zero<<<4096, 256>>>();
    k_prep<<<264, 256>>>(W1, W2);

    // one-time operand conversions
    c_splitHL<<<dim3(4, 1024), 256>>>(adj, pAdjH, pAdjL, 1024, 1024);
    c_split_x<<<dim3(4, 1024), 256>>>(x);
    c_splitHL<<<dim3(1, 512), 256>>>(pWcT, pWcH, pWcL, 132, KAC);
    c_splitHL<<<dim3(1, 512), 256>>>(Wih, pWiH, pWiL, 128, 128);
    c_splitHL<<<dim3(1, 512), 256>>>(Whh, pWhH, pWhL, 128, 128);

    // AX = adj @ x^T : (1024x1024) @ (1024x1024)^T-form
    gemm3<<<dim3(8, 16), 256, SMEM_BYTES>>>(pAdjH, pAdjL, pXH, pXL, pAX, 1024, 1024);

    // ---------------- Encoder: 32 recurrent steps ----------------
    for (int s = 0; s < Ss; s++) {
        c_split_hidT<<<dim3(32, 32), 256>>>();
        gemm3<<<dim3(8, 16), 256, SMEM_BYTES>>>(pAdjH, pAdjL, pHtH, pHtL, pAH, 1024, 1024);
        c_pack_ac<<<8192, KAC>>>(s);
        gemm3<<<dim3(4, 128), 256, SMEM_BYTES>>>(pAcH, pAcL, pWcH, pWcL, pG, KAC, 512);
        k_enc_elem<<<4096, 256>>>(b1, b2);
    }

    // ---------------- Decoder: ctx constant = csum ----------------
    c_splitHL<<<dim3(1, 8192), 256>>>(pCs, pCsH, pCsL, 128, 128);
    gemm3<<<dim3(4, 128), 256, SMEM_BYTES>>>(pCsH, pCsL, pWiH, pWiL, pGc, 128, 512);
    for (int t = 0; t < Ss; t++) {
        gemm3<<<dim3(4, 128), 256, SMEM_BYTES>>>(pHxH, pHxL, pWhH, pWhL, pGd, 128, 512);
        k_lstm<<<4096, 256>>>(bih, bhh);
    }

    k_out<<<4096, 256>>>(out);
}

// round 6
// speedup vs baseline: 2.4264x; 1.1746x over previous
#include <cuda_runtime.h>
#include <cuda_bf16.h>
#include <stdint.h>

// ---------------------------------------------------------------------------
// Problem constants
// ---------------------------------------------------------------------------
#define Bb 8
#define Ss 32
#define Nn 1024
#define Hh 128
#define NBROWS 8192
#define NBH 1048576
#define NHf 131072
#define G3 384

// ---------------------------------------------------------------------------
// Scratch (device globals; no allocation allowed)
// ---------------------------------------------------------------------------
__device__ __align__(16) __nv_bfloat16 g_adjH[1024 * 1024], g_adjL[1024 * 1024];
__device__ __align__(16) __nv_bfloat16 g_xTH[1024 * 1024], g_xTL[1024 * 1024];
__device__ __align__(16) __nv_bfloat16 g_hidTH[1024 * 1024], g_hidTL[1024 * 1024];
__device__ __align__(16) __nv_bfloat16 g_acH[8192 * 128], g_acL[8192 * 128];
__device__ __align__(16) __nv_bfloat16 g_wcH[512 * 128], g_wcL[512 * 128];
__device__ __align__(16) __nv_bfloat16 g_wihH[512 * 128], g_wihL[512 * 128];
__device__ __align__(16) __nv_bfloat16 g_whhH[512 * 128], g_whhL[512 * 128];
__device__ __align__(16) __nv_bfloat16 g_csH[8192 * 128], g_csL[8192 * 128];

__device__ float g_W4[4 * 512];          // Wc rows 0..3, layout [k][gate]
__device__ float g_AX[1024 * 1024];
__device__ float g_G[NBROWS * 512];
__device__ float g_Gc[NBROWS * 512];     // becomes Gfix after k_gfix
__device__ float g_csum[NBH];
__device__ float g_hx[NBH];

// ---------------------------------------------------------------------------
// Helpers
// ---------------------------------------------------------------------------
__device__ __forceinline__ float sigm(float x) { return 1.f / (1.f + __expf(-x)); }

__device__ __forceinline__ uint32_t smem_u32(const void* p) {
    uint32_t a;
    asm("{ .reg .u64 t; cvta.to.shared.u64 t, %1; cvt.u32.u64 %0, t; }" : "=r"(a) : "l"(p));
    return a;
}

__device__ __forceinline__ void splitHL(float v, __nv_bfloat16& h, __nv_bfloat16& l) {
    h = __float2bfloat16(v);
    l = __float2bfloat16(v - __bfloat162float(h));
}
__device__ __forceinline__ uint32_t pack2(float v0, float v1) {
    __nv_bfloat16 a = __float2bfloat16(v0), b = __float2bfloat16(v1);
    return (uint32_t)*(unsigned short*)&a | ((uint32_t)*(unsigned short*)&b << 16);
}
__device__ __forceinline__ uint32_t pack2lo(float v0, float v1) {
    __nv_bfloat16 a = __float2bfloat16(v0);
    __nv_bfloat16 b = __float2bfloat16(v1);
    float l0 = v0 - __bfloat162float(a), l1 = v1 - __bfloat162float(b);
    __nv_bfloat16 c = __float2bfloat16(l0), d = __float2bfloat16(l1);
    return (uint32_t)*(unsigned short*)&c | ((uint32_t)*(unsigned short*)&d << 16);
}

#define MMA_BF16(c, a, b)                                                     \
    asm volatile(                                                             \
        "mma.sync.aligned.m16n8k16.row.col.f32.bf16.bf16.f32 "                \
        "{%0,%1,%2,%3},{%4,%5,%6,%7},{%8,%9},{%0,%1,%2,%3};"                  \
        : "+f"((c)[0]), "+f"((c)[1]), "+f"((c)[2]), "+f"((c)[3])              \
        : "r"((a)[0]), "r"((a)[1]), "r"((a)[2]), "r"((a)[3]),                 \
          "r"((b)[0]), "r"((b)[1]))

#define LDSM4(r0, r1, r2, r3, addr)                                           \
    asm volatile("ldmatrix.sync.aligned.m8n8.x4.shared.b16 {%0,%1,%2,%3},[%4];" \
                 : "=r"(r0), "=r"(r1), "=r"(r2), "=r"(r3) : "r"(addr))

#define CPASYNC16(s, g)                                                       \
    asm volatile("cp.async.cg.shared.global [%0], [%1], 16;" :: "r"(s), "l"(g))
#define CPCOMMIT() asm volatile("cp.async.commit_group;")
#define CPWAIT1()  asm volatile("cp.async.wait_group 1;")
#define CPWAIT0()  asm volatile("cp.async.wait_group 0;")

// ---------------------------------------------------------------------------
// 3xBF16 split GEMM, ldmatrix fragments. C = A @ B^T.
// A: [M][K] bf16 hi/lo, B: [N][K] bf16 hi/lo. BM=64, BN=128, BK=32, 256 thr.
// EPI 0: C fp32 [M][N].  EPI 1: write split AC blocks (encoder fusion).
// grid = (N/128, M/64). K % 32 == 0.
// ---------------------------------------------------------------------------
#define STG_ELEMS 15360         // (64+64+128+128) rows * 40
#define SMEM_BYTES (2 * STG_ELEMS * 2)

template <int EPI>
__global__ void __launch_bounds__(256) gemmA(
    const __nv_bfloat16* __restrict__ Ah, const __nv_bfloat16* __restrict__ Al,
    const __nv_bfloat16* __restrict__ Bh, const __nv_bfloat16* __restrict__ Bl,
    float* __restrict__ C, int K, int N)
{
    extern __shared__ __nv_bfloat16 smem[];
    const uint32_t sb0 = smem_u32(smem);

    const int tid = threadIdx.x;
    const int lane = tid & 31;
    const int wid = tid >> 5;
    const int wm = wid >> 2;
    const int wn = wid & 3;
    const int g = lane >> 2;
    const int ti = lane & 3;

    const int bm = blockIdx.y * 64;
    const int bn = blockIdx.x * 128;

    const int arow = tid >> 2;
    const int akq = tid & 3;

    const int i1 = (lane >> 3) & 1, i2 = lane >> 4, l7 = lane & 7;
    const uint32_t aoff = ((wm * 32 + i1 * 8 + l7) * 40 + i2 * 8) * 2;
    const uint32_t boff = (5120 + (wn * 32 + i2 * 8 + l7) * 40 + i1 * 8) * 2;

    float acc[2][4][4];
#pragma unroll
    for (int i = 0; i < 2; i++)
#pragma unroll
        for (int j = 0; j < 4; j++)
#pragma unroll
            for (int v = 0; v < 4; v++) acc[i][j][v] = 0.f;

    const int nk = K >> 5;

    auto load_stage = [&](int stage, int k0) {
        const uint32_t sb = sb0 + stage * STG_ELEMS * 2;
        {
            const uint32_t so = sb + (arow * 40 + akq * 8) * 2;
            CPASYNC16(so, Ah + (size_t)(bm + arow) * K + k0 + akq * 8);
            CPASYNC16(so + 2560 * 2, Al + (size_t)(bm + arow) * K + k0 + akq * 8);
        }
#pragma unroll
        for (int rep = 0; rep < 2; rep++) {
            const int idx = tid + rep * 256;
            const int brow = idx >> 2;
            const int bkq = idx & 3;
            const uint32_t so = sb + (5120 + brow * 40 + bkq * 8) * 2;
            CPASYNC16(so, Bh + (size_t)(bn + brow) * K + k0 + bkq * 8);
            CPASYNC16(so + 5120 * 2, Bl + (size_t)(bn + brow) * K + k0 + bkq * 8);
        }
        CPCOMMIT();
    };

    load_stage(0, 0);

    for (int kt = 0; kt < nk; kt++) {
        if (kt + 1 < nk) { load_stage((kt + 1) & 1, (kt + 1) * 32); CPWAIT1(); }
        else             { CPWAIT0(); }
        __syncthreads();

        const uint32_t sb = sb0 + (kt & 1) * STG_ELEMS * 2;
#pragma unroll
        for (int q = 0; q < 2; q++) {
            uint32_t ah[2][4], al[2][4], bh[4][2], bl[4][2];
            const uint32_t ka = sb + aoff + q * 32;
            LDSM4(ah[0][0], ah[0][1], ah[0][2], ah[0][3], ka);
            LDSM4(ah[1][0], ah[1][1], ah[1][2], ah[1][3], ka + 1280);
            LDSM4(al[0][0], al[0][1], al[0][2], al[0][3], ka + 5120);
            LDSM4(al[1][0], al[1][1], al[1][2], al[1][3], ka + 5120 + 1280);
            const uint32_t kb = sb + boff + q * 32;
            LDSM4(bh[0][0], bh[0][1], bh[1][0], bh[1][1], kb);
            LDSM4(bh[2][0], bh[2][1], bh[3][0], bh[3][1], kb + 1280);
            LDSM4(bl[0][0], bl[0][1], bl[1][0], bl[1][1], kb + 10240);
            LDSM4(bl[2][0], bl[2][1], bl[3][0], bl[3][1], kb + 10240 + 1280);
#pragma unroll
            for (int mi = 0; mi < 2; mi++)
#pragma unroll
                for (int ni = 0; ni < 4; ni++) {
                    MMA_BF16(acc[mi][ni], ah[mi], bh[ni]);
                    MMA_BF16(acc[mi][ni], ah[mi], bl[ni]);
                    MMA_BF16(acc[mi][ni], al[mi], bh[ni]);
                }
        }
        __syncthreads();
    }

#pragma unroll
    for (int mi = 0; mi < 2; mi++) {
        const int row = bm + wm * 32 + mi * 16 + g;
#pragma unroll
        for (int ni = 0; ni < 4; ni++) {
            const int col = bn + wn * 32 + ni * 8 + 2 * ti;
            if (EPI == 0) {
                *(float2*)(C + (size_t)row * N + col) =
                    make_float2(acc[mi][ni][0], acc[mi][ni][1]);
                *(float2*)(C + (size_t)(row + 8) * N + col) =
                    make_float2(acc[mi][ni][2], acc[mi][ni][3]);
            } else {
                // AC rows (n*8+b), cols h: n = row, b = col>>7, h = col&127
                const int b = col >> 7, h = col & 127;
                const size_t o0 = ((size_t)(row * 8 + b)) * 128 + h;
                const size_t o1 = ((size_t)((row + 8) * 8 + b)) * 128 + h;
                *(uint32_t*)(g_acH + o0) = pack2(acc[mi][ni][0], acc[mi][ni][1]);
                *(uint32_t*)(g_acL + o0) = pack2lo(acc[mi][ni][0], acc[mi][ni][1]);
                *(uint32_t*)(g_acH + o1) = pack2(acc[mi][ni][2], acc[mi][ni][3]);
                *(uint32_t*)(g_acL + o1) = pack2lo(acc[mi][ni][2], acc[mi][ni][3]);
            }
        }
    }
}

// ---------------------------------------------------------------------------
// Persistent fused decoder: 32 LSTM steps in ONE launch.
// grid 128 CTAs (64 rows each) x 512 threads (16 warps: wm 0..1 x wn 0..7).
// hx tile in smem (A operand, rewritten each step), cx in registers,
// Whh streamed L2->smem double-buffered, LSTM fully in-register.
// ---------------------------------------------------------------------------
#define DEC_AH 0
#define DEC_AL 8704
#define DEC_B0 17408
#define DEC_STG 40960
#define DEC_ELEMS (DEC_B0 + 2 * DEC_STG)
#define DEC_SMEM (DEC_ELEMS * 2)

__global__ void __launch_bounds__(512) k_dec(const float* __restrict__ Gfix)
{
    extern __shared__ __nv_bfloat16 sm[];
    const uint32_t sb = smem_u32(sm);

    const int tid = threadIdx.x;
    const int lane = tid & 31;
    const int wid = tid >> 5;
    const int wm = wid >> 3;
    const int wn = wid & 7;
    const int g = lane >> 2;
    const int ti = lane & 3;
    const int bm = blockIdx.x * 64;

    for (int i = tid; i < 8704; i += 512) { sm[DEC_AH + i] = __float2bfloat16(0.f);
                                            sm[DEC_AL + i] = __float2bfloat16(0.f); }

    float cxr[16];
#pragma unroll
    for (int i = 0; i < 16; i++) cxr[i] = 0.f;

    float acc[2][8][4];
#pragma unroll
    for (int mi = 0; mi < 2; mi++)
#pragma unroll
        for (int j = 0; j < 8; j++)
#pragma unroll
            for (int v = 0; v < 4; v++) acc[mi][j][v] = 0.f;

    auto loadB = [&](int kc, int st) {
        const uint32_t base = sb + (DEC_B0 + st * DEC_STG) * 2;
#pragma unroll
        for (int rep = 0; rep < 4; rep++) {
            const int idx = tid + rep * 512;
            const int row = idx >> 2;
            const int qq = idx & 3;
            const uint32_t dst = base + (row * 40 + qq * 8) * 2;
            CPASYNC16(dst, g_whhH + row * 128 + kc * 32 + qq * 8);
            CPASYNC16(dst + 20480 * 2, g_whhL + row * 128 + kc * 32 + qq * 8);
        }
        CPCOMMIT();
    };

    const int i1 = (lane >> 3) & 1, i2 = lane >> 4, l7 = lane & 7;
    const uint32_t aoff = ((wm * 32 + i1 * 8 + l7) * 136 + i2 * 8) * 2;
    const uint32_t boffrel = ((wn * 16 + i2 * 8 + l7) * 40 + i1 * 8) * 2;

    loadB(0, 0);

    for (int step = 0; step < Ss; step++) {
        for (int kc = 0; kc < 4; kc++) {
            const int gi = step * 4 + kc;
            loadB((gi + 1) & 3, (gi + 1) & 1);
            CPWAIT1();
            __syncthreads();
            const uint32_t bbase = sb + (DEC_B0 + (gi & 1) * DEC_STG) * 2;
#pragma unroll
            for (int q = 0; q < 2; q++) {
                uint32_t ah[2][4], al[2][4];
                const uint32_t ka = sb + aoff + (kc * 32 + q * 16) * 2;
                LDSM4(ah[0][0], ah[0][1], ah[0][2], ah[0][3], ka);
                LDSM4(ah[1][0], ah[1][1], ah[1][2], ah[1][3], ka + 4352);
                LDSM4(al[0][0], al[0][1], al[0][2], al[0][3], ka + 17408);
                LDSM4(al[1][0], al[1][1], al[1][2], al[1][3], ka + 17408 + 4352);
#pragma unroll
                for (int pp = 0; pp < 4; pp++) {
                    uint32_t bh[2][2], bl[2][2];
                    const uint32_t kb = bbase + boffrel + q * 32 + pp * 10240;
                    LDSM4(bh[0][0], bh[0][1], bh[1][0], bh[1][1], kb);
                    LDSM4(bl[0][0], bl[0][1], bl[1][0], bl[1][1], kb + 40960);
#pragma unroll
                    for (int mi = 0; mi < 2; mi++)
#pragma unroll
                        for (int jj = 0; jj < 2; jj++) {
                            float* a = acc[mi][pp * 2 + jj];
                            MMA_BF16(a, ah[mi], bh[jj]);
                            MMA_BF16(a, ah[mi], bl[jj]);
                            MMA_BF16(a, al[mi], bh[jj]);
                        }
                }
            }
            __syncthreads();
        }
        const int last = (step == Ss - 1);
#pragma unroll
        for (int mi = 0; mi < 2; mi++)
#pragma unroll
            for (int rh = 0; rh < 2; rh++)
#pragma unroll
                for (int sub = 0; sub < 2; sub++)
#pragma unroll
                    for (int p = 0; p < 2; p++) {
                        const int rowLoc = wm * 32 + mi * 16 + rh * 8 + g;
                        const int h = wn * 16 + sub * 8 + 2 * ti + p;
                        const int grow = bm + rowLoc;
                        const int ci = mi * 8 + rh * 4 + sub * 2 + p;
                        float ig = acc[mi][0 + sub][rh * 2 + p] + Gfix[(size_t)grow * 512 + h];
                        float fg = acc[mi][2 + sub][rh * 2 + p] + Gfix[(size_t)grow * 512 + 128 + h];
                        float gt = acc[mi][4 + sub][rh * 2 + p] + Gfix[(size_t)grow * 512 + 256 + h];
                        float og = acc[mi][6 + sub][rh * 2 + p] + Gfix[(size_t)grow * 512 + 384 + h];
                        ig = sigm(ig); fg = sigm(fg); gt = tanhf(gt); og = sigm(og);
                        const float cx = fg * cxr[ci] + ig * gt;
                        cxr[ci] = cx;
                        const float hxv = og * tanhf(cx);
                        __nv_bfloat16 hh, ll;
                        splitHL(hxv, hh, ll);
                        sm[DEC_AH + rowLoc * 136 + h] = hh;
                        sm[DEC_AL + rowLoc * 136 + h] = ll;
                        if (last) g_hx[(size_t)grow * 128 + h] = hxv;
                        acc[mi][0 + sub][rh * 2 + p] = 0.f;
                        acc[mi][2 + sub][rh * 2 + p] = 0.f;
                        acc[mi][4 + sub][rh * 2 + p] = 0.f;
                        acc[mi][6 + sub][rh * 2 + p] = 0.f;
                    }
        __syncthreads();
    }
}

// ---------------------------------------------------------------------------
// Converters & small kernels
// ---------------------------------------------------------------------------
__global__ void c_splitHL(const float* __restrict__ src,
                          __nv_bfloat16* __restrict__ dH, __nv_bfloat16* __restrict__ dL,
                          int Kc, int Kp)
{
    const int row = blockIdx.y;
    const int k = blockIdx.x * 256 + threadIdx.x;
    if (k >= Kp) return;
    const float v = (k < Kc) ? src[(size_t)row * Kc + k] : 0.f;
    __nv_bfloat16 h, l;
    splitHL(v, h, l);
    dH[(size_t)row * Kp + k] = h;
    dL[(size_t)row * Kp + k] = l;
}

__global__ void c_split_x(const float* __restrict__ x)
{
    const int j = blockIdx.y;
    const int k = blockIdx.x * 256 + threadIdx.x;
    const int s = j >> 5, b = (j >> 2) & 7, f = j & 3;
    const float v = x[((size_t)(b * Ss + s) * Nn + k) * 4 + f];
    __nv_bfloat16 h, l;
    splitHL(v, h, l);
    g_xTH[(size_t)j * 1024 + k] = h;
    g_xTL[(size_t)j * 1024 + k] = l;
}

// wcS (B operand [gate][k], k = Wc rows 4..131) + W4 (Wc rows 0..3, [k][gate])
__global__ void c_wprep(const float* __restrict__ W1, const float* __restrict__ W2)
{
    const int idx = blockIdx.x * 256 + threadIdx.x;
    if (idx < 512 * 128) {
        const int gate = idx >> 7, k = idx & 127;
        const int c = k + 4;
        const float v = (gate < G3) ? W1[c * G3 + gate] : W2[c * Hh + (gate - G3)];
        __nv_bfloat16 h, l;
        splitHL(v, h, l);
        g_wcH[idx] = h;
        g_wcL[idx] = l;
    }
    if (idx < 4 * 512) {
        const int k = idx >> 9, c = idx & 511;
        g_W4[idx] = (c < G3) ? W1[k * G3 + c] : W2[k * Hh + (c - G3)];
    }
}

__global__ void k_zero()
{
    const int idx = blockIdx.x * blockDim.x + threadIdx.x;
    if (idx < NBH) g_csum[idx] = 0.f;
    if (idx < 524288) {
        ((uint32_t*)g_hidTH)[idx] = 0u;
        ((uint32_t*)g_hidTL)[idx] = 0u;
        ((uint32_t*)g_acH)[idx] = 0u;
        ((uint32_t*)g_acL)[idx] = 0u;
    }
    if (idx < NBH) *(float4*)(g_G + (size_t)idx * 4) = make_float4(0.f, 0.f, 0.f, 0.f);
}

// Encoder elementwise: gates with flat-chunk indexing + AX rank-4 correction,
// fused transposed hi/lo split of the new hidden state.
// FIX vs R5: stage the FULL 32x32 tile (4 write slabs), one barrier, then read.
__global__ void k_enc_elem(const float* __restrict__ b1, const float* __restrict__ b2, int s)
{
    __shared__ float t[32][33];
    const int b = blockIdx.x >> 7;
    const int nt = (blockIdx.x >> 2) & 31;
    const int ht = blockIdx.x & 3;
    const int n0 = nt * 32, h0 = ht * 32;
    const int hl = threadIdx.x & 31;
    const int w8 = threadIdx.x >> 5;

#pragma unroll
    for (int q = 0; q < 4; q++) {
        const int nl = w8 + q * 8;
        const int n = n0 + nl;
        const int h = h0 + hl;
        const int j = n * 128 + h;
        const int ji = j + NHf;
        const int ni = ji / G3, ci = ji - ni * G3;
        const int jo = j + 2 * NHf;
        const int no = jo / G3, co = jo - no * G3;
        const int sb4 = s * 32 + b * 4;

        float igp = g_G[(size_t)(ni * 8 + b) * 512 + ci] + b1[ci];
        float ogp = g_G[(size_t)(no * 8 + b) * 512 + co] + b1[co];
        float csp = g_G[(size_t)(n * 8 + b) * 512 + G3 + h] + b2[h];
#pragma unroll
        for (int k = 0; k < 4; k++) {
            igp += g_AX[(size_t)ni * 1024 + sb4 + k] * g_W4[k * 512 + ci];
            ogp += g_AX[(size_t)no * 1024 + sb4 + k] * g_W4[k * 512 + co];
            csp += g_AX[(size_t)n * 1024 + sb4 + k] * g_W4[k * 512 + G3 + h];
        }
        const float hn = sigm(ogp) * tanhf(sigm(igp) * tanhf(csp));
        g_csum[(size_t)(n * 8 + b) * 128 + h] += hn;
        t[hl][nl] = hn;
    }
    __syncthreads();
#pragma unroll
    for (int q = 0; q < 4; q++) {
        const int h2 = w8 + q * 8;
        const float v = t[h2][hl];
        __nv_bfloat16 hh, ll;
        splitHL(v, hh, ll);
        g_hidTH[(size_t)(b * 128 + h0 + h2) * 1024 + n0 + hl] = hh;
        g_hidTL[(size_t)(b * 128 + h0 + h2) * 1024 + n0 + hl] = ll;
    }
}

__global__ void k_gfix(const float* __restrict__ bih, const float* __restrict__ bhh)
{
    const int idx = blockIdx.x * blockDim.x + threadIdx.x;
    if (idx >= NBROWS * 512) return;
    g_Gc[idx] += bih[idx & 511] + bhh[idx & 511];
}

__global__ void k_out(float* __restrict__ out)
{
    const int idx = blockIdx.x * blockDim.x + threadIdx.x;
    if (idx >= NBH) return;
    const int b = idx / (Nn * Hh);
    const int rem = idx - b * (Nn * Hh);
    const int n = rem >> 7;
    const int h = rem & 127;
    out[idx] = g_hx[(size_t)(n * Bb + b) * Hh + h];
}

// ---------------------------------------------------------------------------
// Launch
// ---------------------------------------------------------------------------
extern "C" void kernel_launch(void* const* d_in, const int* in_sizes, int n_in,
                              void* d_out, int out_size)
{
    (void)in_sizes; (void)n_in; (void)out_size;
    const float* x   = (const float*)d_in[0];
    const float* adj = (const float*)d_in[1];
    const float* W1  = (const float*)d_in[2];
    const float* b1  = (const float*)d_in[3];
    const float* W2  = (const float*)d_in[4];
    const float* b2  = (const float*)d_in[5];
    const float* Wih = (const float*)d_in[6];
    const float* Whh = (const float*)d_in[7];
    const float* bih = (const float*)d_in[8];
    const float* bhh = (const float*)d_in[9];
    float* out = (float*)d_out;

    cudaFuncSetAttribute(gemmA<0>, cudaFuncAttributeMaxDynamicSharedMemorySize, SMEM_BYTES);
    cudaFuncSetAttribute(gemmA<1>, cudaFuncAttributeMaxDynamicSharedMemorySize, SMEM_BYTES);
    cudaFuncSetAttribute(k_dec, cudaFuncAttributeMaxDynamicSharedMemorySize, DEC_SMEM);

    __nv_bfloat16 *pAdjH, *pAdjL, *pXH, *pXL, *pHtH, *pHtL, *pAcH, *pAcL;
    __nv_bfloat16 *pWcH, *pWcL, *pWiH, *pWiL, *pWhH, *pWhL, *pCsH, *pCsL;
    float *pAX, *pG, *pGc, *pCs;
    cudaGetSymbolAddress((void**)&pAdjH, g_adjH);
    cudaGetSymbolAddress((void**)&pAdjL, g_adjL);
    cudaGetSymbolAddress((void**)&pXH, g_xTH);
    cudaGetSymbolAddress((void**)&pXL, g_xTL);
    cudaGetSymbolAddress((void**)&pHtH, g_hidTH);
    cudaGetSymbolAddress((void**)&pHtL, g_hidTL);
    cudaGetSymbolAddress((void**)&pAcH, g_acH);
    cudaGetSymbolAddress((void**)&pAcL, g_acL);
    cudaGetSymbolAddress((void**)&pWcH, g_wcH);
    cudaGetSymbolAddress((void**)&pWcL, g_wcL);
    cudaGetSymbolAddress((void**)&pWiH, g_wihH);
    cudaGetSymbolAddress((void**)&pWiL, g_wihL);
    cudaGetSymbolAddress((void**)&pWhH, g_whhH);
    cudaGetSymbolAddress((void**)&pWhL, g_whhL);
    cudaGetSymbolAddress((void**)&pCsH, g_csH);
    cudaGetSymbolAddress((void**)&pCsL, g_csL);
    cudaGetSymbolAddress((void**)&pAX, g_AX);
    cudaGetSymbolAddress((void**)&pG, g_G);
    cudaGetSymbolAddress((void**)&pGc, g_Gc);
    cudaGetSymbolAddress((void**)&pCs, g_csum);

    k_zero<<<4096, 256>>>();
    c_wprep<<<256, 256>>>(W1, W2);
    c_splitHL<<<dim3(4, 1024), 256>>>(adj, pAdjH, pAdjL, 1024, 1024);
    c_split_x<<<dim3(4, 1024), 256>>>(x);
    c_splitHL<<<dim3(1, 512), 256>>>(Wih, pWiH, pWiL, 128, 128);
    c_splitHL<<<dim3(1, 512), 256>>>(Whh, pWhH, pWhL, 128, 128);

    // AX = adj @ x^T (all steps)
    gemmA<0><<<dim3(8, 16), 256, SMEM_BYTES>>>(pAdjH, pAdjL, pXH, pXL, pAX, 1024, 1024);

    // ---------------- Encoder: 32 recurrent steps ----------------
    for (int s = 0; s < Ss; s++) {
        if (s) {
            gemmA<1><<<dim3(8, 16), 256, SMEM_BYTES>>>(pAdjH, pAdjL, pHtH, pHtL,
                                                       pAX /*unused*/, 1024, 1024);
            gemmA<0><<<dim3(4, 128), 256, SMEM_BYTES>>>(pAcH, pAcL, pWcH, pWcL, pG, 128, 512);
        }
        k_enc_elem<<<1024, 256>>>(b1, b2, s);
    }

    // ---------------- Decoder ----------------
    c_splitHL<<<dim3(1, 8192), 256>>>(pCs, pCsH, pCsL, 128, 128);
    gemmA<0><<<dim3(4, 128), 256, SMEM_BYTES>>>(pCsH, pCsL, pWiH, pWiL, pGc, 128, 512);
    k_gfix<<<16384, 256>>>(bih, bhh);
    k_dec<<<128, 512, DEC_SMEM>>>(pGc);

    k_out<<<4096, 256>>>(out);
}

// round 7
// speedup vs baseline: 2.4349x; 1.0035x over previous
#include <cuda_runtime.h>
#include <cuda_bf16.h>
#include <stdint.h>

// ---------------------------------------------------------------------------
// Problem constants
// ---------------------------------------------------------------------------
#define Bb 8
#define Ss 32
#define Nn 1024
#define Hh 128
#define NBROWS 8192
#define NBH 1048576
#define NHf 131072
#define G3 384

// ---------------------------------------------------------------------------
// Scratch (device globals; no allocation allowed)
// ---------------------------------------------------------------------------
__device__ __align__(16) __nv_bfloat16 g_adjH[1024 * 1024], g_adjL[1024 * 1024];
__device__ __align__(16) __nv_bfloat16 g_xTH[1024 * 1024], g_xTL[1024 * 1024];
__device__ __align__(16) __nv_bfloat16 g_hidTH[1024 * 1024], g_hidTL[1024 * 1024];
__device__ __align__(16) __nv_bfloat16 g_acH[8192 * 128], g_acL[8192 * 128];
__device__ __align__(16) __nv_bfloat16 g_wcH[512 * 128], g_wcL[512 * 128];
__device__ __align__(16) __nv_bfloat16 g_wihH[512 * 128], g_wihL[512 * 128];
__device__ __align__(16) __nv_bfloat16 g_whhH[512 * 128], g_whhL[512 * 128];
__device__ __align__(16) __nv_bfloat16 g_csH[8192 * 128], g_csL[8192 * 128];

__device__ float g_W4[4 * 512];          // Wc rows 0..3, layout [k][gate]
__device__ float g_AX[1024 * 1024];
__device__ float g_G[NBROWS * 512];
__device__ float g_Gc[NBROWS * 512];
__device__ float g_csum[NBH];

// ---------------------------------------------------------------------------
// Helpers
// ---------------------------------------------------------------------------
__device__ __forceinline__ float fsigm(float x) {
    return __fdividef(1.f, 1.f + __expf(-x));
}
__device__ __forceinline__ float ftanh(float x) {
    return 1.f - __fdividef(2.f, __expf(2.f * x) + 1.f);
}

__device__ __forceinline__ uint32_t smem_u32(const void* p) {
    uint32_t a;
    asm("{ .reg .u64 t; cvta.to.shared.u64 t, %1; cvt.u32.u64 %0, t; }" : "=r"(a) : "l"(p));
    return a;
}

__device__ __forceinline__ void splitHL(float v, __nv_bfloat16& h, __nv_bfloat16& l) {
    h = __float2bfloat16(v);
    l = __float2bfloat16(v - __bfloat162float(h));
}
__device__ __forceinline__ uint32_t pack2(float v0, float v1) {
    __nv_bfloat16 a = __float2bfloat16(v0), b = __float2bfloat16(v1);
    return (uint32_t)*(unsigned short*)&a | ((uint32_t)*(unsigned short*)&b << 16);
}
__device__ __forceinline__ uint32_t pack2lo(float v0, float v1) {
    __nv_bfloat16 a = __float2bfloat16(v0);
    __nv_bfloat16 b = __float2bfloat16(v1);
    float l0 = v0 - __bfloat162float(a), l1 = v1 - __bfloat162float(b);
    __nv_bfloat16 c = __float2bfloat16(l0), d = __float2bfloat16(l1);
    return (uint32_t)*(unsigned short*)&c | ((uint32_t)*(unsigned short*)&d << 16);
}

#define MMA_BF16(c, a, b)                                                     \
    asm volatile(                                                             \
        "mma.sync.aligned.m16n8k16.row.col.f32.bf16.bf16.f32 "                \
        "{%0,%1,%2,%3},{%4,%5,%6,%7},{%8,%9},{%0,%1,%2,%3};"                  \
        : "+f"((c)[0]), "+f"((c)[1]), "+f"((c)[2]), "+f"((c)[3])              \
        : "r"((a)[0]), "r"((a)[1]), "r"((a)[2]), "r"((a)[3]),                 \
          "r"((b)[0]), "r"((b)[1]))

#define LDSM4(r0, r1, r2, r3, addr)                                           \
    asm volatile("ldmatrix.sync.aligned.m8n8.x4.shared.b16 {%0,%1,%2,%3},[%4];" \
                 : "=r"(r0), "=r"(r1), "=r"(r2), "=r"(r3) : "r"(addr))

#define CPASYNC16(s, g)                                                       \
    asm volatile("cp.async.cg.shared.global [%0], [%1], 16;" :: "r"(s), "l"(g))
#define CPCOMMIT() asm volatile("cp.async.commit_group;")
#define CPWAIT1()  asm volatile("cp.async.wait_group 1;")
#define CPWAIT0()  asm volatile("cp.async.wait_group 0;")

// ---------------------------------------------------------------------------
// 3xBF16 split GEMM, ldmatrix fragments. C = A @ B^T.
// A: [M][K] bf16 hi/lo, B: [N][K] bf16 hi/lo. BM=64, BN template (64/128),
// BK=32, 256 threads. EPI 0: C fp32. EPI 1: split AC blocks (encoder fusion).
// grid = (N/BN, M/64). K % 32 == 0.
// ---------------------------------------------------------------------------
template <int EPI, int BN>
__global__ void __launch_bounds__(256) gemmA(
    const __nv_bfloat16* __restrict__ Ah, const __nv_bfloat16* __restrict__ Al,
    const __nv_bfloat16* __restrict__ Bh, const __nv_bfloat16* __restrict__ Bl,
    float* __restrict__ C, int K, int N)
{
    constexpr int NI = BN / 32;                    // n-frags per warp
    constexpr int STG = 5120 + 2 * BN * 40;        // elems per stage

    extern __shared__ __nv_bfloat16 smem[];
    const uint32_t sb0 = smem_u32(smem);

    const int tid = threadIdx.x;
    const int lane = tid & 31;
    const int wid = tid >> 5;
    const int wm = wid >> 2;
    const int wn = wid & 3;
    const int g = lane >> 2;
    const int ti = lane & 3;

    const int bm = blockIdx.y * 64;
    const int bn = blockIdx.x * BN;

    const int arow = tid >> 2;
    const int akq = tid & 3;

    const int i1 = (lane >> 3) & 1, i2 = lane >> 4, l7 = lane & 7;
    const uint32_t aoff = ((wm * 32 + i1 * 8 + l7) * 40 + i2 * 8) * 2;
    const uint32_t boff = (5120 + (wn * (BN / 4) + i2 * 8 + l7) * 40 + i1 * 8) * 2;

    float acc[2][NI][4];
#pragma unroll
    for (int i = 0; i < 2; i++)
#pragma unroll
        for (int j = 0; j < NI; j++)
#pragma unroll
            for (int v = 0; v < 4; v++) acc[i][j][v] = 0.f;

    const int nk = K >> 5;

    auto load_stage = [&](int stage, int k0) {
        const uint32_t sb = sb0 + stage * STG * 2;
        {
            const uint32_t so = sb + (arow * 40 + akq * 8) * 2;
            CPASYNC16(so, Ah + (size_t)(bm + arow) * K + k0 + akq * 8);
            CPASYNC16(so + 2560 * 2, Al + (size_t)(bm + arow) * K + k0 + akq * 8);
        }
#pragma unroll
        for (int rep = 0; rep < BN / 64; rep++) {
            const int idx = tid + rep * 256;
            const int brow = idx >> 2;
            const int bkq = idx & 3;
            const uint32_t so = sb + (5120 + brow * 40 + bkq * 8) * 2;
            CPASYNC16(so, Bh + (size_t)(bn + brow) * K + k0 + bkq * 8);
            CPASYNC16(so + BN * 40 * 2, Bl + (size_t)(bn + brow) * K + k0 + bkq * 8);
        }
        CPCOMMIT();
    };

    load_stage(0, 0);

    for (int kt = 0; kt < nk; kt++) {
        if (kt + 1 < nk) { load_stage((kt + 1) & 1, (kt + 1) * 32); CPWAIT1(); }
        else             { CPWAIT0(); }
        __syncthreads();

        const uint32_t sb = sb0 + (kt & 1) * STG * 2;
#pragma unroll
        for (int q = 0; q < 2; q++) {
            uint32_t ah[2][4], al[2][4], bh[NI][2], bl[NI][2];
            const uint32_t ka = sb + aoff + q * 32;
            LDSM4(ah[0][0], ah[0][1], ah[0][2], ah[0][3], ka);
            LDSM4(ah[1][0], ah[1][1], ah[1][2], ah[1][3], ka + 1280);
            LDSM4(al[0][0], al[0][1], al[0][2], al[0][3], ka + 5120);
            LDSM4(al[1][0], al[1][1], al[1][2], al[1][3], ka + 5120 + 1280);
            const uint32_t kb = sb + boff + q * 32;
#pragma unroll
            for (int p = 0; p < NI / 2; p++) {
                LDSM4(bh[2 * p][0], bh[2 * p][1], bh[2 * p + 1][0], bh[2 * p + 1][1],
                      kb + p * 1280);
                LDSM4(bl[2 * p][0], bl[2 * p][1], bl[2 * p + 1][0], bl[2 * p + 1][1],
                      kb + BN * 80 + p * 1280);
            }
#pragma unroll
            for (int mi = 0; mi < 2; mi++)
#pragma unroll
                for (int ni = 0; ni < NI; ni++) {
                    MMA_BF16(acc[mi][ni], ah[mi], bh[ni]);
                    MMA_BF16(acc[mi][ni], ah[mi], bl[ni]);
                    MMA_BF16(acc[mi][ni], al[mi], bh[ni]);
                }
        }
        __syncthreads();
    }

#pragma unroll
    for (int mi = 0; mi < 2; mi++) {
        const int row = bm + wm * 32 + mi * 16 + g;
#pragma unroll
        for (int ni = 0; ni < NI; ni++) {
            const int col = bn + wn * (BN / 4) + ni * 8 + 2 * ti;
            if (EPI == 0) {
                *(float2*)(C + (size_t)row * N + col) =
                    make_float2(acc[mi][ni][0], acc[mi][ni][1]);
                *(float2*)(C + (size_t)(row + 8) * N + col) =
                    make_float2(acc[mi][ni][2], acc[mi][ni][3]);
            } else {
                const int b = col >> 7, h = col & 127;
                const size_t o0 = ((size_t)(row * 8 + b)) * 128 + h;
                const size_t o1 = ((size_t)((row + 8) * 8 + b)) * 128 + h;
                *(uint32_t*)(g_acH + o0) = pack2(acc[mi][ni][0], acc[mi][ni][1]);
                *(uint32_t*)(g_acL + o0) = pack2lo(acc[mi][ni][0], acc[mi][ni][1]);
                *(uint32_t*)(g_acH + o1) = pack2(acc[mi][ni][2], acc[mi][ni][3]);
                *(uint32_t*)(g_acL + o1) = pack2lo(acc[mi][ni][2], acc[mi][ni][3]);
            }
        }
    }
}

#define SMEM_B128 (2 * (5120 + 2 * 128 * 40) * 2)   // 61440
#define SMEM_B64  (2 * (5120 + 2 * 64 * 40) * 2)    // 40960

// ---------------------------------------------------------------------------
// Persistent fused decoder: 32 LSTM steps in ONE launch, biases in-kernel,
// final hx written straight to out with the (b,n,h) permutation.
// grid 128 CTAs (64 rows each) x 512 threads (16 warps: wm 0..1 x wn 0..7).
// ---------------------------------------------------------------------------
#define DEC_AH 0
#define DEC_AL 8704
#define DEC_B0 17408
#define DEC_STG 40960
#define DEC_ELEMS (DEC_B0 + 2 * DEC_STG)
#define DEC_SMEM (DEC_ELEMS * 2)

__global__ void __launch_bounds__(512) k_dec(const float* __restrict__ Gc,
                                             const float* __restrict__ bih,
                                             const float* __restrict__ bhh,
                                             float* __restrict__ out)
{
    extern __shared__ __nv_bfloat16 sm[];
    __shared__ float sbias[512];
    const uint32_t sb = smem_u32(sm);

    const int tid = threadIdx.x;
    const int lane = tid & 31;
    const int wid = tid >> 5;
    const int wm = wid >> 3;
    const int wn = wid & 7;
    const int g = lane >> 2;
    const int ti = lane & 3;
    const int bm = blockIdx.x * 64;

    if (tid < 512) sbias[tid] = bih[tid] + bhh[tid];
    for (int i = tid; i < 8704; i += 512) { sm[DEC_AH + i] = __float2bfloat16(0.f);
                                            sm[DEC_AL + i] = __float2bfloat16(0.f); }

    float cxr[16];
#pragma unroll
    for (int i = 0; i < 16; i++) cxr[i] = 0.f;

    float acc[2][8][4];
#pragma unroll
    for (int mi = 0; mi < 2; mi++)
#pragma unroll
        for (int j = 0; j < 8; j++)
#pragma unroll
            for (int v = 0; v < 4; v++) acc[mi][j][v] = 0.f;

    auto loadB = [&](int kc, int st) {
        const uint32_t base = sb + (DEC_B0 + st * DEC_STG) * 2;
#pragma unroll
        for (int rep = 0; rep < 4; rep++) {
            const int idx = tid + rep * 512;
            const int row = idx >> 2;
            const int qq = idx & 3;
            const uint32_t dst = base + (row * 40 + qq * 8) * 2;
            CPASYNC16(dst, g_whhH + row * 128 + kc * 32 + qq * 8);
            CPASYNC16(dst + 20480 * 2, g_whhL + row * 128 + kc * 32 + qq * 8);
        }
        CPCOMMIT();
    };

    const int i1 = (lane >> 3) & 1, i2 = lane >> 4, l7 = lane & 7;
    const uint32_t aoff = ((wm * 32 + i1 * 8 + l7) * 136 + i2 * 8) * 2;
    const uint32_t boffrel = ((wn * 16 + i2 * 8 + l7) * 40 + i1 * 8) * 2;

    loadB(0, 0);

    for (int step = 0; step < Ss; step++) {
        for (int kc = 0; kc < 4; kc++) {
            const int gi = step * 4 + kc;
            loadB((gi + 1) & 3, (gi + 1) & 1);
            CPWAIT1();
            __syncthreads();
            const uint32_t bbase = sb + (DEC_B0 + (gi & 1) * DEC_STG) * 2;
#pragma unroll
            for (int q = 0; q < 2; q++) {
                uint32_t ah[2][4], al[2][4];
                const uint32_t ka = sb + aoff + (kc * 32 + q * 16) * 2;
                LDSM4(ah[0][0], ah[0][1], ah[0][2], ah[0][3], ka);
                LDSM4(ah[1][0], ah[1][1], ah[1][2], ah[1][3], ka + 4352);
                LDSM4(al[0][0], al[0][1], al[0][2], al[0][3], ka + 17408);
                LDSM4(al[1][0], al[1][1], al[1][2], al[1][3], ka + 17408 + 4352);
#pragma unroll
                for (int pp = 0; pp < 4; pp++) {
                    uint32_t bh[2][2], bl[2][2];
                    const uint32_t kb = bbase + boffrel + q * 32 + pp * 10240;
                    LDSM4(bh[0][0], bh[0][1], bh[1][0], bh[1][1], kb);
                    LDSM4(bl[0][0], bl[0][1], bl[1][0], bl[1][1], kb + 40960);
#pragma unroll
                    for (int mi = 0; mi < 2; mi++)
#pragma unroll
                        for (int jj = 0; jj < 2; jj++) {
                            float* a = acc[mi][pp * 2 + jj];
                            MMA_BF16(a, ah[mi], bh[jj]);
                            MMA_BF16(a, ah[mi], bl[jj]);
                            MMA_BF16(a, al[mi], bh[jj]);
                        }
                }
            }
            __syncthreads();
        }
        const int last = (step == Ss - 1);
#pragma unroll
        for (int mi = 0; mi < 2; mi++)
#pragma unroll
            for (int rh = 0; rh < 2; rh++)
#pragma unroll
                for (int sub = 0; sub < 2; sub++)
#pragma unroll
                    for (int p = 0; p < 2; p++) {
                        const int rowLoc = wm * 32 + mi * 16 + rh * 8 + g;
                        const int h = wn * 16 + sub * 8 + 2 * ti + p;
                        const int grow = bm + rowLoc;
                        const int ci = mi * 8 + rh * 4 + sub * 2 + p;
                        float ig = acc[mi][0 + sub][rh * 2 + p] + Gc[(size_t)grow * 512 + h] + sbias[h];
                        float fg = acc[mi][2 + sub][rh * 2 + p] + Gc[(size_t)grow * 512 + 128 + h] + sbias[128 + h];
                        float gt = acc[mi][4 + sub][rh * 2 + p] + Gc[(size_t)grow * 512 + 256 + h] + sbias[256 + h];
                        float og = acc[mi][6 + sub][rh * 2 + p] + Gc[(size_t)grow * 512 + 384 + h] + sbias[384 + h];
                        ig = fsigm(ig); fg = fsigm(fg); gt = ftanh(gt); og = fsigm(og);
                        const float cx = fg * cxr[ci] + ig * gt;
                        cxr[ci] = cx;
                        const float hxv = og * ftanh(cx);
                        __nv_bfloat16 hh, ll;
                        splitHL(hxv, hh, ll);
                        sm[DEC_AH + rowLoc * 136 + h] = hh;
                        sm[DEC_AL + rowLoc * 136 + h] = ll;
                        if (last) {
                            const int b = grow & 7, n = grow >> 3;
                            out[((size_t)b * 1024 + n) * 128 + h] = hxv;
                        }
                        acc[mi][0 + sub][rh * 2 + p] = 0.f;
                        acc[mi][2 + sub][rh * 2 + p] = 0.f;
                        acc[mi][4 + sub][rh * 2 + p] = 0.f;
                        acc[mi][6 + sub][rh * 2 + p] = 0.f;
                    }
        __syncthreads();
    }
}

// ---------------------------------------------------------------------------
// Converters & small kernels
// ---------------------------------------------------------------------------
__global__ void c_splitHL(const float* __restrict__ src,
                          __nv_bfloat16* __restrict__ dH, __nv_bfloat16* __restrict__ dL,
                          int Kc, int Kp)
{
    const int row = blockIdx.y;
    const int k = blockIdx.x * 256 + threadIdx.x;
    if (k >= Kp) return;
    const float v = (k < Kc) ? src[(size_t)row * Kc + k] : 0.f;
    __nv_bfloat16 h, l;
    splitHL(v, h, l);
    dH[(size_t)row * Kp + k] = h;
    dL[(size_t)row * Kp + k] = l;
}

__global__ void c_split_x(const float* __restrict__ x)
{
    const int j = blockIdx.y;
    const int k = blockIdx.x * 256 + threadIdx.x;
    const int s = j >> 5, b = (j >> 2) & 7, f = j & 3;
    const float v = x[((size_t)(b * Ss + s) * Nn + k) * 4 + f];
    __nv_bfloat16 h, l;
    splitHL(v, h, l);
    g_xTH[(size_t)j * 1024 + k] = h;
    g_xTL[(size_t)j * 1024 + k] = l;
}

__global__ void c_wprep(const float* __restrict__ W1, const float* __restrict__ W2)
{
    const int idx = blockIdx.x * 256 + threadIdx.x;
    if (idx < 512 * 128) {
        const int gate = idx >> 7, k = idx & 127;
        const int c = k + 4;
        const float v = (gate < G3) ? W1[c * G3 + gate] : W2[c * Hh + (gate - G3)];
        __nv_bfloat16 h, l;
        splitHL(v, h, l);
        g_wcH[idx] = h;
        g_wcL[idx] = l;
    }
    if (idx < 4 * 512) {
        const int k = idx >> 9, c = idx & 511;
        g_W4[idx] = (c < G3) ? W1[k * G3 + c] : W2[k * Hh + (c - G3)];
    }
}

__global__ void k_zero()
{
    const int idx = blockIdx.x * blockDim.x + threadIdx.x;
    if (idx < NBH) g_csum[idx] = 0.f;
    if (idx < 524288) {
        ((uint32_t*)g_hidTH)[idx] = 0u;
        ((uint32_t*)g_hidTL)[idx] = 0u;
        ((uint32_t*)g_acH)[idx] = 0u;
        ((uint32_t*)g_acL)[idx] = 0u;
    }
    if (idx < NBH) *(float4*)(g_G + (size_t)idx * 4) = make_float4(0.f, 0.f, 0.f, 0.f);
}

// Encoder elementwise: flat-chunk gate indexing + AX rank-4 correction,
// fused transposed hi/lo split; on last step also writes split csum.
__global__ void k_enc_elem(const float* __restrict__ b1, const float* __restrict__ b2,
                           int s, int last)
{
    __shared__ float t[32][33];
    const int b = blockIdx.x >> 7;
    const int nt = (blockIdx.x >> 2) & 31;
    const int ht = blockIdx.x & 3;
    const int n0 = nt * 32, h0 = ht * 32;
    const int hl = threadIdx.x & 31;
    const int w8 = threadIdx.x >> 5;

#pragma unroll
    for (int q = 0; q < 4; q++) {
        const int nl = w8 + q * 8;
        const int n = n0 + nl;
        const int h = h0 + hl;
        const int j = n * 128 + h;
        const int ji = j + NHf;
        const int ni = ji / G3, ci = ji - ni * G3;
        const int jo = j + 2 * NHf;
        const int no = jo / G3, co = jo - no * G3;
        const int sb4 = s * 32 + b * 4;

        float igp = g_G[(size_t)(ni * 8 + b) * 512 + ci] + b1[ci];
        float ogp = g_G[(size_t)(no * 8 + b) * 512 + co] + b1[co];
        float csp = g_G[(size_t)(n * 8 + b) * 512 + G3 + h] + b2[h];
#pragma unroll
        for (int k = 0; k < 4; k++) {
            igp += g_AX[(size_t)ni * 1024 + sb4 + k] * g_W4[k * 512 + ci];
            ogp += g_AX[(size_t)no * 1024 + sb4 + k] * g_W4[k * 512 + co];
            csp += g_AX[(size_t)n * 1024 + sb4 + k] * g_W4[k * 512 + G3 + h];
        }
        const float hn = fsigm(ogp) * ftanh(fsigm(igp) * ftanh(csp));
        const size_t co2 = (size_t)(n * 8 + b) * 128 + h;
        const float cs2 = g_csum[co2] + hn;
        g_csum[co2] = cs2;
        if (last) {
            __nv_bfloat16 ch, cl;
            splitHL(cs2, ch, cl);
            g_csH[co2] = ch;
            g_csL[co2] = cl;
        }
        t[hl][nl] = hn;
    }
    __syncthreads();
#pragma unroll
    for (int q = 0; q < 4; q++) {
        const int h2 = w8 + q * 8;
        const float v = t[h2][hl];
        __nv_bfloat16 hh, ll;
        splitHL(v, hh, ll);
        g_hidTH[(size_t)(b * 128 + h0 + h2) * 1024 + n0 + hl] = hh;
        g_hidTL[(size_t)(b * 128 + h0 + h2) * 1024 + n0 + hl] = ll;
    }
}

// ---------------------------------------------------------------------------
// Launch
// ---------------------------------------------------------------------------
extern "C" void kernel_launch(void* const* d_in, const int* in_sizes, int n_in,
                              void* d_out, int out_size)
{
    (void)in_sizes; (void)n_in; (void)out_size;
    const float* x   = (const float*)d_in[0];
    const float* adj = (const float*)d_in[1];
    const float* W1  = (const float*)d_in[2];
    const float* b1  = (const float*)d_in[3];
    const float* W2  = (const float*)d_in[4];
    const float* b2  = (const float*)d_in[5];
    const float* Wih = (const float*)d_in[6];
    const float* Whh = (const float*)d_in[7];
    const float* bih = (const float*)d_in[8];
    const float* bhh = (const float*)d_in[9];
    float* out = (float*)d_out;

    cudaFuncSetAttribute(gemmA<0, 128>, cudaFuncAttributeMaxDynamicSharedMemorySize, SMEM_B128);
    cudaFuncSetAttribute(gemmA<0, 64>, cudaFuncAttributeMaxDynamicSharedMemorySize, SMEM_B64);
    cudaFuncSetAttribute(gemmA<1, 64>, cudaFuncAttributeMaxDynamicSharedMemorySize, SMEM_B64);
    cudaFuncSetAttribute(k_dec, cudaFuncAttributeMaxDynamicSharedMemorySize, DEC_SMEM);

    __nv_bfloat16 *pAdjH, *pAdjL, *pXH, *pXL, *pHtH, *pHtL, *pAcH, *pAcL;
    __nv_bfloat16 *pWcH, *pWcL, *pWiH, *pWiL, *pWhH, *pWhL, *pCsH, *pCsL;
    float *pAX, *pG, *pGc;
    cudaGetSymbolAddress((void**)&pAdjH, g_adjH);
    cudaGetSymbolAddress((void**)&pAdjL, g_adjL);
    cudaGetSymbolAddress((void**)&pXH, g_xTH);
    cudaGetSymbolAddress((void**)&pXL, g_xTL);
    cudaGetSymbolAddress((void**)&pHtH, g_hidTH);
    cudaGetSymbolAddress((void**)&pHtL, g_hidTL);
    cudaGetSymbolAddress((void**)&pAcH, g_acH);
    cudaGetSymbolAddress((void**)&pAcL, g_acL);
    cudaGetSymbolAddress((void**)&pWcH, g_wcH);
    cudaGetSymbolAddress((void**)&pWcL, g_wcL);
    cudaGetSymbolAddress((void**)&pWiH, g_wihH);
    cudaGetSymbolAddress((void**)&pWiL, g_wihL);
    cudaGetSymbolAddress((void**)&pWhH, g_whhH);
    cudaGetSymbolAddress((void**)&pWhL, g_whhL);
    cudaGetSymbolAddress((void**)&pCsH, g_csH);
    cudaGetSymbolAddress((void**)&pCsL, g_csL);
    cudaGetSymbolAddress((void**)&pAX, g_AX);
    cudaGetSymbolAddress((void**)&pG, g_G);
    cudaGetSymbolAddress((void**)&pGc, g_Gc);

    k_zero<<<4096, 256>>>();
    c_wprep<<<256, 256>>>(W1, W2);
    c_splitHL<<<dim3(4, 1024), 256>>>(adj, pAdjH, pAdjL, 1024, 1024);
    c_split_x<<<dim3(4, 1024), 256>>>(x);
    c_splitHL<<<dim3(1, 512), 256>>>(Wih, pWiH, pWiL, 128, 128);
    c_splitHL<<<dim3(1, 512), 256>>>(Whh, pWhH, pWhL, 128, 128);

    // AX = adj @ x^T (all steps)
    gemmA<0, 64><<<dim3(16, 16), 256, SMEM_B64>>>(pAdjH, pAdjL, pXH, pXL, pAX, 1024, 1024);

    // ---------------- Encoder: 32 recurrent steps ----------------
    for (int s = 0; s < Ss; s++) {
        if (s) {
            gemmA<1, 64><<<dim3(16, 16), 256, SMEM_B64>>>(pAdjH, pAdjL, pHtH, pHtL,
                                                          pAX /*unused*/, 1024, 1024);
            gemmA<0, 128><<<dim3(4, 128), 256, SMEM_B128>>>(pAcH, pAcL, pWcH, pWcL,
                                                            pG, 128, 512);
        }
        k_enc_elem<<<1024, 256>>>(b1, b2, s, s == Ss - 1);
    }

    // ---------------- Decoder ----------------
    gemmA<0, 128><<<dim3(4, 128), 256, SMEM_B128>>>(pCsH, pCsL, pWiH, pWiL, pGc, 128, 512);
    k_dec<<<128, 512, DEC_SMEM>>>(pGc, bih, bhh, out);
}

// round 10
// speedup vs baseline: 2.5961x; 1.0662x over previous
#include <cuda_runtime.h>
#include <cuda_bf16.h>
#include <stdint.h>

// ---------------------------------------------------------------------------
// Problem constants
// ---------------------------------------------------------------------------
#define Bb 8
#define Ss 32
#define Nn 1024
#define Hh 128
#define NBROWS 8192
#define NBH 1048576
#define NHf 131072
#define G3 384

// ---------------------------------------------------------------------------
// Scratch (device globals; no allocation allowed). Node-major rows r = n*8+b.
// ---------------------------------------------------------------------------
__device__ __align__(16) __nv_bfloat16 g_adjH[1024 * 1024], g_adjL[1024 * 1024];
__device__ __align__(16) __nv_bfloat16 g_xTH[1024 * 1024], g_xTL[1024 * 1024];
__device__ __align__(16) __nv_bfloat16 g_hidTH[1024 * 1024], g_hidTL[1024 * 1024];
__device__ __align__(16) __nv_bfloat16 g_wcH[512 * 128], g_wcL[512 * 128];
__device__ __align__(16) __nv_bfloat16 g_wihH[512 * 128], g_wihL[512 * 128];
__device__ __align__(16) __nv_bfloat16 g_whhH[512 * 128], g_whhL[512 * 128];
__device__ __align__(16) __nv_bfloat16 g_csH[8192 * 128], g_csL[8192 * 128];

__device__ float g_W4[4 * 512];          // Wc rows 0..3, layout [k][gate]
__device__ float g_AX[1024 * 1024];
__device__ float g_G[NBROWS * 512];
__device__ float g_Gc[NBROWS * 512];
__device__ float g_csum[NBH];

// ---------------------------------------------------------------------------
// Helpers
// ---------------------------------------------------------------------------
__device__ __forceinline__ float fsigm(float x) {
    return __fdividef(1.f, 1.f + __expf(-x));
}
__device__ __forceinline__ float ftanh(float x) {
    return 1.f - __fdividef(2.f, __expf(2.f * x) + 1.f);
}

__device__ __forceinline__ uint32_t smem_u32(const void* p) {
    uint32_t a;
    asm("{ .reg .u64 t; cvta.to.shared.u64 t, %1; cvt.u32.u64 %0, t; }" : "=r"(a) : "l"(p));
    return a;
}

__device__ __forceinline__ void splitHL(float v, __nv_bfloat16& h, __nv_bfloat16& l) {
    h = __float2bfloat16(v);
    l = __float2bfloat16(v - __bfloat162float(h));
}
__device__ __forceinline__ uint32_t pack2(float v0, float v1) {
    __nv_bfloat16 a = __float2bfloat16(v0), b = __float2bfloat16(v1);
    return (uint32_t)*(unsigned short*)&a | ((uint32_t)*(unsigned short*)&b << 16);
}
__device__ __forceinline__ uint32_t pack2lo(float v0, float v1) {
    __nv_bfloat16 a = __float2bfloat16(v0);
    __nv_bfloat16 b = __float2bfloat16(v1);
    float l0 = v0 - __bfloat162float(a), l1 = v1 - __bfloat162float(b);
    __nv_bfloat16 c = __float2bfloat16(l0), d = __float2bfloat16(l1);
    return (uint32_t)*(unsigned short*)&c | ((uint32_t)*(unsigned short*)&d << 16);
}

#define MMA_BF16(c, a, b)                                                     \
    asm volatile(                                                             \
        "mma.sync.aligned.m16n8k16.row.col.f32.bf16.bf16.f32 "                \
        "{%0,%1,%2,%3},{%4,%5,%6,%7},{%8,%9},{%0,%1,%2,%3};"                  \
        : "+f"((c)[0]), "+f"((c)[1]), "+f"((c)[2]), "+f"((c)[3])              \
        : "r"((a)[0]), "r"((a)[1]), "r"((a)[2]), "r"((a)[3]),                 \
          "r"((b)[0]), "r"((b)[1]))

#define LDSM4(r0, r1, r2, r3, addr)                                           \
    asm volatile("ldmatrix.sync.aligned.m8n8.x4.shared.b16 {%0,%1,%2,%3},[%4];" \
                 : "=r"(r0), "=r"(r1), "=r"(r2), "=r"(r3) : "r"(addr))

#define CPASYNC16(s, g)                                                       \
    asm volatile("cp.async.cg.shared.global [%0], [%1], 16;" :: "r"(s), "l"(g))
#define CPCOMMIT() asm volatile("cp.async.commit_group;")
#define CPWAIT1()  asm volatile("cp.async.wait_group 1;")
#define CPWAIT0()  asm volatile("cp.async.wait_group 0;")

// ---------------------------------------------------------------------------
// 3xBF16 split GEMM (standalone, fp32 C epilogue). C = A @ B^T.
// BM=64, BN template (64/128), BK=32, 256 threads. grid = (N/BN, M/64).
// ---------------------------------------------------------------------------
template <int BN>
__global__ void __launch_bounds__(256) gemmA(
    const __nv_bfloat16* __restrict__ Ah, const __nv_bfloat16* __restrict__ Al,
    const __nv_bfloat16* __restrict__ Bh, const __nv_bfloat16* __restrict__ Bl,
    float* __restrict__ C, int K, int N)
{
    constexpr int NI = BN / 32;
    constexpr int STG = 5120 + 2 * BN * 40;

    extern __shared__ __nv_bfloat16 smem[];
    const uint32_t sb0 = smem_u32(smem);

    const int tid = threadIdx.x;
    const int lane = tid & 31;
    const int wid = tid >> 5;
    const int wm = wid >> 2;
    const int wn = wid & 3;
    const int g = lane >> 2;
    const int ti = lane & 3;

    const int bm = blockIdx.y * 64;
    const int bn = blockIdx.x * BN;

    const int arow = tid >> 2;
    const int akq = tid & 3;

    const int i1 = (lane >> 3) & 1, i2 = lane >> 4, l7 = lane & 7;
    const uint32_t aoff = ((wm * 32 + i1 * 8 + l7) * 40 + i2 * 8) * 2;
    const uint32_t boff = (5120 + (wn * (BN / 4) + i2 * 8 + l7) * 40 + i1 * 8) * 2;

    float acc[2][NI][4];
#pragma unroll
    for (int i = 0; i < 2; i++)
#pragma unroll
        for (int j = 0; j < NI; j++)
#pragma unroll
            for (int v = 0; v < 4; v++) acc[i][j][v] = 0.f;

    const int nk = K >> 5;

    auto load_stage = [&](int stage, int k0) {
        const uint32_t sb = sb0 + stage * STG * 2;
        {
            const uint32_t so = sb + (arow * 40 + akq * 8) * 2;
            CPASYNC16(so, Ah + (size_t)(bm + arow) * K + k0 + akq * 8);
            CPASYNC16(so + 2560 * 2, Al + (size_t)(bm + arow) * K + k0 + akq * 8);
        }
#pragma unroll
        for (int rep = 0; rep < BN / 64; rep++) {
            const int idx = tid + rep * 256;
            const int brow = idx >> 2;
            const int bkq = idx & 3;
            const uint32_t so = sb + (5120 + brow * 40 + bkq * 8) * 2;
            CPASYNC16(so, Bh + (size_t)(bn + brow) * K + k0 + bkq * 8);
            CPASYNC16(so + BN * 40 * 2, Bl + (size_t)(bn + brow) * K + k0 + bkq * 8);
        }
        CPCOMMIT();
    };

    load_stage(0, 0);

    for (int kt = 0; kt < nk; kt++) {
        if (kt + 1 < nk) { load_stage((kt + 1) & 1, (kt + 1) * 32); CPWAIT1(); }
        else             { CPWAIT0(); }
        __syncthreads();

        const uint32_t sb = sb0 + (kt & 1) * STG * 2;
#pragma unroll
        for (int q = 0; q < 2; q++) {
            uint32_t ah[2][4], al[2][4], bh[NI][2], bl[NI][2];
            const uint32_t ka = sb + aoff + q * 32;
            LDSM4(ah[0][0], ah[0][1], ah[0][2], ah[0][3], ka);
            LDSM4(ah[1][0], ah[1][1], ah[1][2], ah[1][3], ka + 1280);
            LDSM4(al[0][0], al[0][1], al[0][2], al[0][3], ka + 5120);
            LDSM4(al[1][0], al[1][1], al[1][2], al[1][3], ka + 5120 + 1280);
            const uint32_t kb = sb + boff + q * 32;
#pragma unroll
            for (int p = 0; p < NI / 2; p++) {
                LDSM4(bh[2 * p][0], bh[2 * p][1], bh[2 * p + 1][0], bh[2 * p + 1][1],
                      kb + p * 1280);
                LDSM4(bl[2 * p][0], bl[2 * p][1], bl[2 * p + 1][0], bl[2 * p + 1][1],
                      kb + BN * 80 + p * 1280);
            }
#pragma unroll
            for (int mi = 0; mi < 2; mi++)
#pragma unroll
                for (int ni = 0; ni < NI; ni++) {
                    MMA_BF16(acc[mi][ni], ah[mi], bh[ni]);
                    MMA_BF16(acc[mi][ni], ah[mi], bl[ni]);
                    MMA_BF16(acc[mi][ni], al[mi], bh[ni]);
                }
        }
        __syncthreads();
    }

#pragma unroll
    for (int mi = 0; mi < 2; mi++) {
        const int row = bm + wm * 32 + mi * 16 + g;
#pragma unroll
        for (int ni = 0; ni < NI; ni++) {
            const int col = bn + wn * (BN / 4) + ni * 8 + 2 * ti;
            *(float2*)(C + (size_t)row * N + col) =
                make_float2(acc[mi][ni][0], acc[mi][ni][1]);
            *(float2*)(C + (size_t)(row + 8) * N + col) =
                make_float2(acc[mi][ni][2], acc[mi][ni][3]);
        }
    }
}

#define SMEM_B128 (2 * (5120 + 2 * 128 * 40) * 2)   // 61440
#define SMEM_B64  (2 * (5120 + 2 * 64 * 40) * 2)    // 40960

// ---------------------------------------------------------------------------
// FUSED per-step encoder kernel: one CTA computes an AC tile (64 n-rows x
// 128 (b,h)-cols, K=1024, 3-pass) into SMEM, then G tile (64 x 512, K=128)
// streaming Wc from L2. grid = (16 n-tiles, 8 batches) = 128 CTAs, 256 thr.
// SMEM phase1: 2 stages x 15360 elems. phase2: AC_hi@0 (64x136), AC_lo@8704,
// Wc double-buffer @17408 (2 x 10240 elems). Total 37888 elems = 75776 B.
// ---------------------------------------------------------------------------
#define STG1 15360
#define SMEM_STEP 75776

__global__ void __launch_bounds__(256) k_step()
{
    extern __shared__ __nv_bfloat16 smem[];
    const uint32_t sb0 = smem_u32(smem);

    const int tid = threadIdx.x;
    const int lane = tid & 31;
    const int wid = tid >> 5;
    const int wm = wid >> 2;
    const int wn = wid & 3;
    const int g = lane >> 2;
    const int ti = lane & 3;
    const int bm = blockIdx.x * 64;       // n-tile base
    const int b = blockIdx.y;             // batch

    const __nv_bfloat16* BH = g_hidTH + (size_t)b * 128 * 1024;
    const __nv_bfloat16* BL = g_hidTL + (size_t)b * 128 * 1024;

    const int arow = tid >> 2;
    const int akq = tid & 3;
    const int i1 = (lane >> 3) & 1, i2 = lane >> 4, l7 = lane & 7;
    const uint32_t aoff = ((wm * 32 + i1 * 8 + l7) * 40 + i2 * 8) * 2;
    const uint32_t boff = (5120 + (wn * 32 + i2 * 8 + l7) * 40 + i1 * 8) * 2;

    float acc[2][4][4];
#pragma unroll
    for (int i = 0; i < 2; i++)
#pragma unroll
        for (int j = 0; j < 4; j++)
#pragma unroll
            for (int v = 0; v < 4; v++) acc[i][j][v] = 0.f;

    // ---------------- phase 1: AC = adj[bm:+64] @ hidT_b^T ----------------
    auto load_stage = [&](int stage, int k0) {
        const uint32_t sb = sb0 + stage * STG1 * 2;
        {
            const uint32_t so = sb + (arow * 40 + akq * 8) * 2;
            CPASYNC16(so, g_adjH + (size_t)(bm + arow) * 1024 + k0 + akq * 8);
            CPASYNC16(so + 2560 * 2, g_adjL + (size_t)(bm + arow) * 1024 + k0 + akq * 8);
        }
#pragma unroll
        for (int rep = 0; rep < 2; rep++) {
            const int idx = tid + rep * 256;
            const int brow = idx >> 2;
            const int bkq = idx & 3;
            const uint32_t so = sb + (5120 + brow * 40 + bkq * 8) * 2;
            CPASYNC16(so, BH + (size_t)brow * 1024 + k0 + bkq * 8);
            CPASYNC16(so + 10240, BL + (size_t)brow * 1024 + k0 + bkq * 8);
        }
        CPCOMMIT();
    };

    load_stage(0, 0);

    for (int kt = 0; kt < 32; kt++) {
        if (kt + 1 < 32) { load_stage((kt + 1) & 1, (kt + 1) * 32); CPWAIT1(); }
        else             { CPWAIT0(); }
        __syncthreads();

        const uint32_t sb = sb0 + (kt & 1) * STG1 * 2;
#pragma unroll
        for (int q = 0; q < 2; q++) {
            uint32_t ah[2][4], al[2][4], bh[4][2], bl[4][2];
            const uint32_t ka = sb + aoff + q * 32;
            LDSM4(ah[0][0], ah[0][1], ah[0][2], ah[0][3], ka);
            LDSM4(ah[1][0], ah[1][1], ah[1][2], ah[1][3], ka + 1280);
            LDSM4(al[0][0], al[0][1], al[0][2], al[0][3], ka + 5120);
            LDSM4(al[1][0], al[1][1], al[1][2], al[1][3], ka + 5120 + 1280);
            const uint32_t kb = sb + boff + q * 32;
#pragma unroll
            for (int p = 0; p < 2; p++) {
                LDSM4(bh[2 * p][0], bh[2 * p][1], bh[2 * p + 1][0], bh[2 * p + 1][1],
                      kb + p * 1280);
                LDSM4(bl[2 * p][0], bl[2 * p][1], bl[2 * p + 1][0], bl[2 * p + 1][1],
                      kb + 10240 + p * 1280);
            }
#pragma unroll
            for (int mi = 0; mi < 2; mi++)
#pragma unroll
                for (int ni = 0; ni < 4; ni++) {
                    MMA_BF16(acc[mi][ni], ah[mi], bh[ni]);
                    MMA_BF16(acc[mi][ni], ah[mi], bl[ni]);
                    MMA_BF16(acc[mi][ni], al[mi], bh[ni]);
                }
        }
        __syncthreads();
    }

    // ---- AC -> SMEM (split hi/lo), rows stride 136 ----
#pragma unroll
    for (int mi = 0; mi < 2; mi++) {
        const int row = wm * 32 + mi * 16 + g;
#pragma unroll
        for (int ni = 0; ni < 4; ni++) {
            const int col = wn * 32 + ni * 8 + 2 * ti;
            const uint32_t o0 = (uint32_t)(row * 136 + col) * 2;
            const uint32_t o1 = (uint32_t)((row + 8) * 136 + col) * 2;
            asm volatile("st.shared.b32 [%0], %1;" :: "r"(sb0 + o0),
                         "r"(pack2(acc[mi][ni][0], acc[mi][ni][1])));
            asm volatile("st.shared.b32 [%0], %1;" :: "r"(sb0 + 17408 + o0),
                         "r"(pack2lo(acc[mi][ni][0], acc[mi][ni][1])));
            asm volatile("st.shared.b32 [%0], %1;" :: "r"(sb0 + o1),
                         "r"(pack2(acc[mi][ni][2], acc[mi][ni][3])));
            asm volatile("st.shared.b32 [%0], %1;" :: "r"(sb0 + 17408 + o1),
                         "r"(pack2lo(acc[mi][ni][2], acc[mi][ni][3])));
        }
    }
    __syncthreads();

    // ---------------- phase 2: G = AC @ Wc^T (K=128) ----------------
    auto loadWc = [&](int idx, int st) {
        const uint32_t base = sb0 + (17408 + st * 10240) * 2;
        const int nc2 = idx >> 2, kc2 = idx & 3;
#pragma unroll
        for (int rep = 0; rep < 2; rep++) {
            const int e = tid + rep * 256;
            const int row = e >> 2, q4 = e & 3;
            const uint32_t dst = base + (row * 40 + q4 * 8) * 2;
            CPASYNC16(dst, g_wcH + (nc2 * 128 + row) * 128 + kc2 * 32 + q4 * 8);
            CPASYNC16(dst + 5120 * 2, g_wcL + (nc2 * 128 + row) * 128 + kc2 * 32 + q4 * 8);
        }
        CPCOMMIT();
    };

    const uint32_t aoff2 = ((wm * 32 + i1 * 8 + l7) * 136 + i2 * 8) * 2;
    const uint32_t boff2 = ((wn * 32 + i2 * 8 + l7) * 40 + i1 * 8) * 2;

    loadWc(0, 0);

    for (int nc = 0; nc < 4; nc++) {
#pragma unroll
        for (int i = 0; i < 2; i++)
#pragma unroll
            for (int j = 0; j < 4; j++)
#pragma unroll
                for (int v = 0; v < 4; v++) acc[i][j][v] = 0.f;

        for (int kc = 0; kc < 4; kc++) {
            const int gi = nc * 4 + kc;
            if (gi < 15) { loadWc(gi + 1, (gi + 1) & 1); CPWAIT1(); }
            else         { CPWAIT0(); }
            __syncthreads();
            const uint32_t wcb = sb0 + (17408 + (gi & 1) * 10240) * 2;
#pragma unroll
            for (int q = 0; q < 2; q++) {
                uint32_t ah[2][4], al[2][4], bh[4][2], bl[4][2];
                const uint32_t ka = sb0 + aoff2 + (kc * 32 + q * 16) * 2;
                LDSM4(ah[0][0], ah[0][1], ah[0][2], ah[0][3], ka);
                LDSM4(ah[1][0], ah[1][1], ah[1][2], ah[1][3], ka + 4352);
                LDSM4(al[0][0], al[0][1], al[0][2], al[0][3], ka + 17408);
                LDSM4(al[1][0], al[1][1], al[1][2], al[1][3], ka + 17408 + 4352);
                const uint32_t kb = wcb + boff2 + q * 32;
#pragma unroll
                for (int p = 0; p < 2; p++) {
                    LDSM4(bh[2 * p][0], bh[2 * p][1], bh[2 * p + 1][0], bh[2 * p + 1][1],
                          kb + p * 1280);
                    LDSM4(bl[2 * p][0], bl[2 * p][1], bl[2 * p + 1][0], bl[2 * p + 1][1],
                          kb + 10240 + p * 1280);
                }
#pragma unroll
                for (int mi = 0; mi < 2; mi++)
#pragma unroll
                    for (int ni = 0; ni < 4; ni++) {
                        MMA_BF16(acc[mi][ni], ah[mi], bh[ni]);
                        MMA_BF16(acc[mi][ni], ah[mi], bl[ni]);
                        MMA_BF16(acc[mi][ni], al[mi], bh[ni]);
                    }
            }
            __syncthreads();
        }

        // write G chunk (node-major rows r = n*8+b)
#pragma unroll
        for (int mi = 0; mi < 2; mi++) {
            const int n0 = bm + wm * 32 + mi * 16 + g;
#pragma unroll
            for (int ni = 0; ni < 4; ni++) {
                const int col = nc * 128 + wn * 32 + ni * 8 + 2 * ti;
                *(float2*)(g_G + ((size_t)n0 * 8 + b) * 512 + col) =
                    make_float2(acc[mi][ni][0], acc[mi][ni][1]);
                *(float2*)(g_G + ((size_t)(n0 + 8) * 8 + b) * 512 + col) =
                    make_float2(acc[mi][ni][2], acc[mi][ni][3]);
            }
        }
    }
}

// ---------------------------------------------------------------------------
// Persistent fused decoder: 32 LSTM steps in ONE launch (R7-proven).
// grid 128 CTAs x 512 threads. Writes the (b,n,h)-permuted output directly.
// ---------------------------------------------------------------------------
#define DEC_AH 0
#define DEC_AL 8704
#define DEC_B0 17408
#define DEC_STG 40960
#define DEC_ELEMS (DEC_B0 + 2 * DEC_STG)
#define DEC_SMEM (DEC_ELEMS * 2)

__global__ void __launch_bounds__(512) k_dec(const float* __restrict__ Gc,
                                             const float* __restrict__ bih,
                                             const float* __restrict__ bhh,
                                             float* __restrict__ out)
{
    extern __shared__ __nv_bfloat16 sm[];
    __shared__ float sbias[512];
    const uint32_t sb = smem_u32(sm);

    const int tid = threadIdx.x;
    const int lane = tid & 31;
    const int wid = tid >> 5;
    const int wm = wid >> 3;
    const int wn = wid & 7;
    const int g = lane >> 2;
    const int ti = lane & 3;
    const int bm = blockIdx.x * 64;

    if (tid < 512) sbias[tid] = bih[tid] + bhh[tid];
    for (int i = tid; i < 8704; i += 512) { sm[DEC_AH + i] = __float2bfloat16(0.f);
                                            sm[DEC_AL + i] = __float2bfloat16(0.f); }

    float cxr[16];
#pragma unroll
    for (int i = 0; i < 16; i++) cxr[i] = 0.f;

    float acc[2][8][4];
#pragma unroll
    for (int mi = 0; mi < 2; mi++)
#pragma unroll
        for (int j = 0; j < 8; j++)
#pragma unroll
            for (int v = 0; v < 4; v++) acc[mi][j][v] = 0.f;

    auto loadB = [&](int kc, int st) {
        const uint32_t base = sb + (DEC_B0 + st * DEC_STG) * 2;
#pragma unroll
        for (int rep = 0; rep < 4; rep++) {
            const int idx = tid + rep * 512;
            const int row = idx >> 2;
            const int qq = idx & 3;
            const uint32_t dst = base + (row * 40 + qq * 8) * 2;
            CPASYNC16(dst, g_whhH + row * 128 + kc * 32 + qq * 8);
            CPASYNC16(dst + 20480 * 2, g_whhL + row * 128 + kc * 32 + qq * 8);
        }
        CPCOMMIT();
    };

    const int i1 = (lane >> 3) & 1, i2 = lane >> 4, l7 = lane & 7;
    const uint32_t aoff = ((wm * 32 + i1 * 8 + l7) * 136 + i2 * 8) * 2;
    const uint32_t boffrel = ((wn * 16 + i2 * 8 + l7) * 40 + i1 * 8) * 2;

    loadB(0, 0);

    for (int step = 0; step < Ss; step++) {
        for (int kc = 0; kc < 4; kc++) {
            const int gi = step * 4 + kc;
            loadB((gi + 1) & 3, (gi + 1) & 1);
            CPWAIT1();
            __syncthreads();
            const uint32_t bbase = sb + (DEC_B0 + (gi & 1) * DEC_STG) * 2;
#pragma unroll
            for (int q = 0; q < 2; q++) {
                uint32_t ah[2][4], al[2][4];
                const uint32_t ka = sb + aoff + (kc * 32 + q * 16) * 2;
                LDSM4(ah[0][0], ah[0][1], ah[0][2], ah[0][3], ka);
                LDSM4(ah[1][0], ah[1][1], ah[1][2], ah[1][3], ka + 4352);
                LDSM4(al[0][0], al[0][1], al[0][2], al[0][3], ka + 17408);
                LDSM4(al[1][0], al[1][1], al[1][2], al[1][3], ka + 17408 + 4352);
#pragma unroll
                for (int pp = 0; pp < 4; pp++) {
                    uint32_t bh[2][2], bl[2][2];
                    const uint32_t kb = bbase + boffrel + q * 32 + pp * 10240;
                    LDSM4(bh[0][0], bh[0][1], bh[1][0], bh[1][1], kb);
                    LDSM4(bl[0][0], bl[0][1], bl[1][0], bl[1][1], kb + 40960);
#pragma unroll
                    for (int mi = 0; mi < 2; mi++)
#pragma unroll
                        for (int jj = 0; jj < 2; jj++) {
                            float* a = acc[mi][pp * 2 + jj];
                            MMA_BF16(a, ah[mi], bh[jj]);
                            MMA_BF16(a, ah[mi], bl[jj]);
                            MMA_BF16(a, al[mi], bh[jj]);
                        }
                }
            }
            __syncthreads();
        }
        const int last = (step == Ss - 1);
#pragma unroll
        for (int mi = 0; mi < 2; mi++)
#pragma unroll
            for (int rh = 0; rh < 2; rh++)
#pragma unroll
                for (int sub = 0; sub < 2; sub++)
#pragma unroll
                    for (int p = 0; p < 2; p++) {
                        const int rowLoc = wm * 32 + mi * 16 + rh * 8 + g;
                        const int h = wn * 16 + sub * 8 + 2 * ti + p;
                        const int grow = bm + rowLoc;
                        const int ci = mi * 8 + rh * 4 + sub * 2 + p;
                        float ig = acc[mi][0 + sub][rh * 2 + p] + Gc[(size_t)grow * 512 + h] + sbias[h];
                        float fg = acc[mi][2 + sub][rh * 2 + p] + Gc[(size_t)grow * 512 + 128 + h] + sbias[128 + h];
                        float gt = acc[mi][4 + sub][rh * 2 + p] + Gc[(size_t)grow * 512 + 256 + h] + sbias[256 + h];
                        float og = acc[mi][6 + sub][rh * 2 + p] + Gc[(size_t)grow * 512 + 384 + h] + sbias[384 + h];
                        ig = fsigm(ig); fg = fsigm(fg); gt = ftanh(gt); og = fsigm(og);
                        const float cx = fg * cxr[ci] + ig * gt;
                        cxr[ci] = cx;
                        const float hxv = og * ftanh(cx);
                        __nv_bfloat16 hh, ll;
                        splitHL(hxv, hh, ll);
                        sm[DEC_AH + rowLoc * 136 + h] = hh;
                        sm[DEC_AL + rowLoc * 136 + h] = ll;
                        if (last) {
                            const int b = grow & 7, n = grow >> 3;
                            out[((size_t)b * 1024 + n) * 128 + h] = hxv;
                        }
                        acc[mi][0 + sub][rh * 2 + p] = 0.f;
                        acc[mi][2 + sub][rh * 2 + p] = 0.f;
                        acc[mi][4 + sub][rh * 2 + p] = 0.f;
                        acc[mi][6 + sub][rh * 2 + p] = 0.f;
                    }
        __syncthreads();
    }
}

// ---------------------------------------------------------------------------
// Converters & small kernels
// ---------------------------------------------------------------------------
__global__ void c_splitHL(const float* __restrict__ src,
                          __nv_bfloat16* __restrict__ dH, __nv_bfloat16* __restrict__ dL,
                          int Kc, int Kp)
{
    const int row = blockIdx.y;
    const int k = blockIdx.x * 256 + threadIdx.x;
    if (k >= Kp) return;
    const float v = (k < Kc) ? src[(size_t)row * Kc + k] : 0.f;
    __nv_bfloat16 h, l;
    splitHL(v, h, l);
    dH[(size_t)row * Kp + k] = h;
    dL[(size_t)row * Kp + k] = l;
}

__global__ void c_split_x(const float* __restrict__ x)
{
    const int j = blockIdx.y;
    const int k = blockIdx.x * 256 + threadIdx.x;
    const int s = j >> 5, b = (j >> 2) & 7, f = j & 3;
    const float v = x[((size_t)(b * Ss + s) * Nn + k) * 4 + f];
    __nv_bfloat16 h, l;
    splitHL(v, h, l);
    g_xTH[(size_t)j * 1024 + k] = h;
    g_xTL[(size_t)j * 1024 + k] = l;
}

__global__ void c_wprep(const float* __restrict__ W1, const float* __restrict__ W2)
{
    const int idx = blockIdx.x * 256 + threadIdx.x;
    if (idx < 512 * 128) {
        const int gate = idx >> 7, k = idx & 127;
        const int c = k + 4;
        const float v = (gate < G3) ? W1[c * G3 + gate] : W2[c * Hh + (gate - G3)];
        __nv_bfloat16 h, l;
        splitHL(v, h, l);
        g_wcH[idx] = h;
        g_wcL[idx] = l;
    }
    if (idx < 4 * 512) {
        const int k = idx >> 9, c = idx & 511;
        g_W4[idx] = (c < G3) ? W1[k * G3 + c] : W2[k * Hh + (c - G3)];
    }
}

__global__ void k_zero()
{
    const int idx = blockIdx.x * blockDim.x + threadIdx.x;   // 1M threads
    *(float4*)(g_G + (size_t)idx * 4) = make_float4(0.f, 0.f, 0.f, 0.f);
    g_csum[idx] = 0.f;
}

// Encoder elementwise: flat-chunk gate indexing + AX rank-4 correction,
// fused transposed hi/lo split; on last step also writes split csum.
__global__ void k_enc_elem(const float* __restrict__ b1, const float* __restrict__ b2,
                           int s, int last)
{
    __shared__ float t[32][33];
    const int b = blockIdx.x >> 7;
    const int nt = (blockIdx.x >> 2) & 31;
    const int ht = blockIdx.x & 3;
    const int n0 = nt * 32, h0 = ht * 32;
    const int hl = threadIdx.x & 31;
    const int w8 = threadIdx.x >> 5;

#pragma unroll
    for (int q = 0; q < 4; q++) {
        const int nl = w8 + q * 8;
        const int n = n0 + nl;
        const int h = h0 + hl;
        const int j = n * 128 + h;
        const int ji = j + NHf;
        const int ni = ji / G3, ci = ji - ni * G3;
        const int jo = j + 2 * NHf;
        const int no = jo / G3, co = jo - no * G3;
        const int sb4 = s * 32 + b * 4;

        float igp = g_G[(size_t)(ni * 8 + b) * 512 + ci] + b1[ci];
        float ogp = g_G[(size_t)(no * 8 + b) * 512 + co] + b1[co];
        float csp = g_G[(size_t)(n * 8 + b) * 512 + G3 + h] + b2[h];
#pragma unroll
        for (int k = 0; k < 4; k++) {
            igp += g_AX[(size_t)ni * 1024 + sb4 + k] * g_W4[k * 512 + ci];
            ogp += g_AX[(size_t)no * 1024 + sb4 + k] * g_W4[k * 512 + co];
            csp += g_AX[(size_t)n * 1024 + sb4 + k] * g_W4[k * 512 + G3 + h];
        }
        const float hn = fsigm(ogp) * ftanh(fsigm(igp) * ftanh(csp));
        const size_t co2 = (size_t)(n * 8 + b) * 128 + h;
        const float cs2 = g_csum[co2] + hn;
        g_csum[co2] = cs2;
        if (last) {
            __nv_bfloat16 ch, cl;
            splitHL(cs2, ch, cl);
            g_csH[co2] = ch;
            g_csL[co2] = cl;
        }
        t[hl][nl] = hn;
    }
    __syncthreads();
#pragma unroll
    for (int q = 0; q < 4; q++) {
        const int h2 = w8 + q * 8;
        const float v = t[h2][hl];
        __nv_bfloat16 hh, ll;
        splitHL(v, hh, ll);
        g_hidTH[(size_t)(b * 128 + h0 + h2) * 1024 + n0 + hl] = hh;
        g_hidTL[(size_t)(b * 128 + h0 + h2) * 1024 + n0 + hl] = ll;
    }
}

// ---------------------------------------------------------------------------
// Launch (single stream — stream creation allocates device memory and is
// banned; concurrency instead comes from full-wave fused kernels).
// ---------------------------------------------------------------------------
extern "C" void kernel_launch(void* const* d_in, const int* in_sizes, int n_in,
                              void* d_out, int out_size)
{
    (void)in_sizes; (void)n_in; (void)out_size;
    const float* x   = (const float*)d_in[0];
    const float* adj = (const float*)d_in[1];
    const float* W1  = (const float*)d_in[2];
    const float* b1  = (const float*)d_in[3];
    const float* W2  = (const float*)d_in[4];
    const float* b2  = (const float*)d_in[5];
    const float* Wih = (const float*)d_in[6];
    const float* Whh = (const float*)d_in[7];
    const float* bih = (const float*)d_in[8];
    const float* bhh = (const float*)d_in[9];
    float* out = (float*)d_out;

    cudaFuncSetAttribute(gemmA<128>, cudaFuncAttributeMaxDynamicSharedMemorySize, SMEM_B128);
    cudaFuncSetAttribute(gemmA<64>, cudaFuncAttributeMaxDynamicSharedMemorySize, SMEM_B64);
    cudaFuncSetAttribute(k_step, cudaFuncAttributeMaxDynamicSharedMemorySize, SMEM_STEP);
    cudaFuncSetAttribute(k_dec, cudaFuncAttributeMaxDynamicSharedMemorySize, DEC_SMEM);

    __nv_bfloat16 *pAdjH, *pAdjL, *pXH, *pXL, *pWiH, *pWiL, *pWhH, *pWhL, *pCsH, *pCsL;
    float *pAX, *pGc;
    cudaGetSymbolAddress((void**)&pAdjH, g_adjH);
    cudaGetSymbolAddress((void**)&pAdjL, g_adjL);
    cudaGetSymbolAddress((void**)&pXH, g_xTH);
    cudaGetSymbolAddress((void**)&pXL, g_xTL);
    cudaGetSymbolAddress((void**)&pWiH, g_wihH);
    cudaGetSymbolAddress((void**)&pWiL, g_wihL);
    cudaGetSymbolAddress((void**)&pWhH, g_whhH);
    cudaGetSymbolAddress((void**)&pWhL, g_whhL);
    cudaGetSymbolAddress((void**)&pCsH, g_csH);
    cudaGetSymbolAddress((void**)&pCsL, g_csL);
    cudaGetSymbolAddress((void**)&pAX, g_AX);
    cudaGetSymbolAddress((void**)&pGc, g_Gc);

    k_zero<<<4096, 256>>>();
    c_wprep<<<256, 256>>>(W1, W2);
    c_splitHL<<<dim3(4, 1024), 256>>>(adj, pAdjH, pAdjL, 1024, 1024);
    c_split_x<<<dim3(4, 1024), 256>>>(x);
    c_splitHL<<<dim3(1, 512), 256>>>(Wih, pWiH, pWiL, 128, 128);
    c_splitHL<<<dim3(1, 512), 256>>>(Whh, pWhH, pWhL, 128, 128);

    // AX = adj @ x^T (all steps)
    gemmA<64><<<dim3(16, 16), 256, SMEM_B64>>>(pAdjH, pAdjL, pXH, pXL, pAX, 1024, 1024);

    // ---------------- Encoder: 32 recurrent steps (2 kernels each) --------
    for (int s = 0; s < Ss; s++) {
        if (s) k_step<<<dim3(16, 8), 256, SMEM_STEP>>>();
        k_enc_elem<<<1024, 256>>>(b1, b2, s, s == Ss - 1);
    }

    // ---------------- Decoder ----------------
    gemmA<128><<<dim3(4, 128), 256, SMEM_B128>>>(pCsH, pCsL, pWiH, pWiL, pGc, 128, 512);
    k_dec<<<128, 512, DEC_SMEM>>>(pGc, bih, bhh, out);
}